// round 6
// baseline (speedup 1.0000x reference)
#include <cuda_runtime.h>
#include <cuda_bf16.h>
#include <math.h>

#define BATCH 16
#define CIN   512
#define FH    50
#define FW    50
#define HW    2500
#define NANCH 9
#define NTOT  (HW*NANCH)
#define PRE   512
#define POST  128
#define IMGW  800.0f
#define IMGH  800.0f
#define KB    4               // input channels per staging step

typedef unsigned long long ull;

// ---- packed f32x2 ops (per-lane IEEE rn -> bit-identical to scalar) ----
#define F2MUL(d,a,b)   asm("mul.rn.f32x2 %0,%1,%2;"    : "=l"(d) : "l"(a), "l"(b))
#define F2ADD(d,a,b)   asm("add.rn.f32x2 %0,%1,%2;"    : "=l"(d) : "l"(a), "l"(b))
#define F2SUB(d,a,b)   asm("sub.rn.f32x2 %0,%1,%2;"    : "=l"(d) : "l"(a), "l"(b))
#define F2FMA(d,a,b,c) asm("fma.rn.f32x2 %0,%1,%2,%3;" : "=l"(d) : "l"(a), "l"(b), "l"(c))
#define F2PACK(d,lo,hi) asm("mov.b64 %0,{%1,%2};" : "=l"(d) : "f"(lo), "f"(hi))
#define F2UNPACK(lo,hi,v) asm("mov.b64 {%0,%1},%2;" : "=f"(lo), "=f"(hi) : "l"(v))

// packed Kahan (same op sequence as scalar KAHAN_ADD, per lane)
#define K2ADD(s,c,p) do { ull _y,_t,_u;                \
    F2SUB(_y,(p),(c)); F2ADD(_t,(s),_y);               \
    F2SUB(_u,_t,(s));  F2SUB((c),_u,_y); (s)=_t;       \
} while (0)

// scalar Kahan (K2/K4, unchanged)
#define KAHAN_ADD(s, c, p) do {                        \
    float _y = __fsub_rn((p), (c));                    \
    float _t = __fadd_rn((s), _y);                     \
    (c) = __fsub_rn(__fsub_rn(_t, (s)), _y);           \
    (s) = _t;                                          \
} while (0)

#define COMP(v,i) ((i)==0?(v).x:((i)==1?(v).y:((i)==2?(v).z:(v).w)))

// ---------------- device scratch ----------------
__device__ float g_shared[(size_t)BATCH*CIN*HW];
__device__ float g_scores[(size_t)BATCH*NTOT];
__device__ int   g_topidx[BATCH*PRE];
__device__ float g_topscore[BATCH*PRE];
__device__ float g_w1t[4608*512];                  // w1 transposed: [ic*9+t][oc]

// ================= K0: transpose w1 [oc][4608] -> [4608][oc] ============
__global__ __launch_bounds__(256) void transpose_w1_kernel(
    const float* __restrict__ w1)
{
    __shared__ float t[32][33];
    const int r0 = blockIdx.x * 32;
    const int c0 = blockIdx.y * 32;
    const int tx = threadIdx.x & 31, ty = threadIdx.x >> 5;
#pragma unroll
    for (int i = 0; i < 4; i++)
        t[ty + i*8][tx] = w1[(size_t)(c0 + ty + i*8) * 4608 + r0 + tx];
    __syncthreads();
#pragma unroll
    for (int i = 0; i < 4; i++)
        g_w1t[(size_t)(r0 + ty + i*8) * 512 + c0 + tx] = t[tx][ty + i*8];
}

// ================= K1: 3x3 conv, packed f32x2, 32oc x 128px tile ========
#define BPX 128
#define BOC 32
__global__ __launch_bounds__(128) void conv3x3_kernel(
    const float* __restrict__ x, const float* __restrict__ b1)
{
    __shared__ float Ws[KB*9][BOC];                     // 4.6 KB
    __shared__ __align__(16) float XsC[KB][3][6*50];    // 14.4 KB, 3 dx-shifts

    const int bidx = blockIdx.z;
    const int oc0  = blockIdx.y * BOC;
    const int p0   = blockIdx.x * BPX;
    const int tid  = threadIdx.x;
    const int tx   = tid & 15;      // 16 pixel groups (8 px each)
    const int ty   = tid >> 4;      // 8 oc groups (4 oc each)

    const int r0    = p0 / FW - 1;            // first tap row stored
    const int pbase = p0 + tx * 8;
    const int Lb    = pbase - FW * r0 - FW;   // index for dy=-1 of pixel pbase

    ull acc[4][4], cmp[4][4];                 // [oc i][pixel-pair]
#pragma unroll
    for (int i = 0; i < 4; i++)
#pragma unroll
        for (int j = 0; j < 4; j++) { acc[i][j] = 0ULL; cmp[i][j] = 0ULL; }

    const float* xb = x + (size_t)bidx * CIN * HW;

    for (int ic0 = 0; ic0 < CIN; ic0 += KB) {
        // stage weights: KB*9 rows x 32 oc = 288 float4
        for (int j = tid; j < KB*9*(BOC/4); j += 128) {
            int row = j >> 3, o4 = (j & 7) << 2;
            *(float4*)&Ws[row][o4] =
                *(const float4*)&g_w1t[(size_t)(ic0*9 + row) * 512 + oc0 + o4];
        }
        // stage x: 3 shifted linear copies, rows r0..r0+5, zero-padded
        for (int j = tid; j < KB*3*300; j += 128) {
            int k  = j / 900;
            int r  = j % 900;
            int s  = r / 300;
            int li = r % 300;
            int ri = r0 + li / FW;
            int cc = li % FW + s - 1;
            XsC[k][s][li] = (ri >= 0 && ri < FH && cc >= 0 && cc < FW)
                    ? xb[(size_t)(ic0 + k) * HW + ri*FW + cc] : 0.f;
        }
        __syncthreads();

#pragma unroll
        for (int k = 0; k < KB; k++) {
            float4 wv4[9];
#pragma unroll
            for (int t = 0; t < 9; t++)
                wv4[t] = *(const float4*)&Ws[k*9 + t][ty*4];

#pragma unroll
            for (int h = 0; h < 2; h++) {        // two pixel-pair halves
                ull xq[2][9];
#pragma unroll
                for (int q = 0; q < 2; q++) {
                    const int off = Lb + (h*2 + q) * 2;   // even -> 8B aligned
#pragma unroll
                    for (int t = 0; t < 9; t++)
                        xq[q][t] = *(const ull*)&XsC[k][t % 3][off + (t/3)*FW];
                }
#pragma unroll
                for (int i = 0; i < 4; i++) {
                    ull wp[9];
#pragma unroll
                    for (int t = 0; t < 9; t++) {
                        float w = COMP(wv4[t], i);
                        F2PACK(wp[t], w, w);
                    }
#pragma unroll
                    for (int q = 0; q < 2; q++) {
                        ull d0, d1, d2, d;
                        F2MUL(d0, wp[0], xq[q][0]);
                        F2FMA(d0, wp[1], xq[q][1], d0);
                        F2FMA(d0, wp[2], xq[q][2], d0);
                        F2MUL(d1, wp[3], xq[q][3]);
                        F2FMA(d1, wp[4], xq[q][4], d1);
                        F2FMA(d1, wp[5], xq[q][5], d1);
                        F2MUL(d2, wp[6], xq[q][6]);
                        F2FMA(d2, wp[7], xq[q][7], d2);
                        F2FMA(d2, wp[8], xq[q][8], d2);
                        F2ADD(d, d0, d1);
                        F2ADD(d, d, d2);
                        K2ADD(acc[i][h*2 + q], cmp[i][h*2 + q], d);
                    }
                }
            }
        }
        __syncthreads();
    }

    // epilogue: r = acc - cmp (packed), unpack, +bias, relu, store
#pragma unroll
    for (int i = 0; i < 4; i++) {
        const int oc = oc0 + ty*4 + i;
        const float bias = b1[oc];
        float* op = g_shared + ((size_t)bidx*CIN + oc)*HW;
#pragma unroll
        for (int pr = 0; pr < 4; pr++) {
            ull r;
            F2SUB(r, acc[i][pr], cmp[i][pr]);
            float lo, hi;
            F2UNPACK(lo, hi, r);
            int pA = pbase + pr*2, pB = pA + 1;
            if (pA < HW) op[pA] = fmaxf(__fadd_rn(lo, bias), 0.f);
            if (pB < HW) op[pB] = fmaxf(__fadd_rn(hi, bias), 0.f);
        }
    }
}

// ================= K2: 1x1 cls conv (512->9) + sigmoid ==================
__global__ __launch_bounds__(256) void cls_kernel(
    const float* __restrict__ w2, const float* __restrict__ b2)
{
    __shared__ float w2s[9][512];
    const int b = blockIdx.y;
    const int p = blockIdx.x * 256 + threadIdx.x;
    for (int i = threadIdx.x; i < 9*512; i += 256)
        w2s[i/512][i%512] = w2[i];
    __syncthreads();
    if (p >= HW) return;

    float acc[9], cmp[9];
#pragma unroll
    for (int a = 0; a < 9; a++) { acc[a] = 0.f; cmp[a] = 0.f; }

    const float* sp = g_shared + (size_t)b * CIN * HW + p;
    for (int c = 0; c < CIN; c++) {
        float v = sp[(size_t)c * HW];
#pragma unroll
        for (int a = 0; a < 9; a++)
            KAHAN_ADD(acc[a], cmp[a], __fmul_rn(v, w2s[a][c]));
    }
    float* outp = g_scores + (size_t)b * NTOT + (size_t)p * 9;
#pragma unroll
    for (int a = 0; a < 9; a++) {
        float logit = __fadd_rn(__fsub_rn(acc[a], cmp[a]), b2[a]);
        double sg = 1.0 / (1.0 + exp(-(double)logit));
        outp[a] = (float)sg;
    }
}

// ================= K3: exact per-image top-512 (sorted) ==================
__global__ __launch_bounds__(1024) void topk_kernel()
{
    extern __shared__ unsigned char smraw[];
    unsigned int* hist = (unsigned int*)smraw;
    unsigned int* csum = hist + 32768;
    unsigned long long* cand = (unsigned long long*)(csum + 1024);
    __shared__ int s_tb, s_cntgt, s_thr, s_cnt;

    const int b = blockIdx.x, tid = threadIdx.x;
    const float* sc = g_scores + (size_t)b * NTOT;

    for (int i = tid; i < 32768; i += 1024) hist[i] = 0;
    __syncthreads();
    for (int i = tid; i < NTOT; i += 1024) {
        unsigned int bits = __float_as_uint(sc[i]);
        atomicAdd(&hist[bits >> 15], 1u);
    }
    __syncthreads();
    { unsigned int cs = 0;
#pragma unroll 4
      for (int k = 0; k < 32; k++) cs += hist[tid*32 + k];
      csum[tid] = cs; }
    __syncthreads();
    if (tid == 0) {
        unsigned int accum = 0;
        int ch = 1023;
        for (; ch > 0; ch--) { if (accum + csum[ch] >= PRE) break; accum += csum[ch]; }
        int bk = ch*32 + 31;
        for (; bk > ch*32; bk--) { if (accum + hist[bk] >= PRE) break; accum += hist[bk]; }
        s_tb = bk; s_cntgt = (int)accum;
    }
    __syncthreads();
    const int tb = s_tb, cntgt = s_cntgt;

    for (int i = tid; i < 32768; i += 1024) hist[i] = 0;
    __syncthreads();
    for (int i = tid; i < NTOT; i += 1024) {
        unsigned int bits = __float_as_uint(sc[i]);
        if ((int)(bits >> 15) == tb) atomicAdd(&hist[bits & 0x7FFF], 1u);
    }
    __syncthreads();
    { unsigned int cs = 0;
#pragma unroll 4
      for (int k = 0; k < 32; k++) cs += hist[tid*32 + k];
      csum[tid] = cs; }
    __syncthreads();
    if (tid == 0) {
        unsigned int accum = (unsigned int)cntgt;
        int ch = 1023;
        for (; ch > 0; ch--) { if (accum + csum[ch] >= PRE) break; accum += csum[ch]; }
        int bk = ch*32 + 31;
        for (; bk > ch*32; bk--) { if (accum + hist[bk] >= PRE) break; accum += hist[bk]; }
        s_thr = (tb << 15) | bk;
        s_cnt = 0;
    }
    __syncthreads();
    const unsigned int thrbits = (unsigned int)s_thr;

    for (int i = tid; i < NTOT; i += 1024) {
        unsigned int bits = __float_as_uint(sc[i]);
        if (bits >= thrbits) {
            int pos = atomicAdd(&s_cnt, 1);
            if (pos < 1024)
                cand[pos] = ((unsigned long long)bits << 32) |
                            (unsigned long long)(0xFFFFFFFFu - (unsigned int)i);
        }
    }
    __syncthreads();
    int cnt = s_cnt; if (cnt > 1024) cnt = 1024;
    if (tid >= cnt) cand[tid] = 0ULL;
    __syncthreads();

    for (int k = 2; k <= 1024; k <<= 1) {
        for (int j = k >> 1; j > 0; j >>= 1) {
            int ixj = tid ^ j;
            if (ixj > tid) {
                unsigned long long a = cand[tid], c = cand[ixj];
                bool up = ((tid & k) == 0);
                bool sw = up ? (a < c) : (a > c);
                if (sw) { cand[tid] = c; cand[ixj] = a; }
            }
            __syncthreads();
        }
    }

    if (tid < PRE) {
        unsigned long long key = cand[tid];
        unsigned int idx = 0xFFFFFFFFu - (unsigned int)(key & 0xFFFFFFFFull);
        g_topidx[b*PRE + tid]   = (int)idx;
        g_topscore[b*PRE + tid] = __uint_as_float((unsigned int)(key >> 32));
    }
}

// ====== K4: offsets@selected + anchors + decode + clip + NMS + output ====
#define W3S_FLOATS (36*513)
__global__ __launch_bounds__(512) void proposal_kernel(
    const float* __restrict__ w3, const float* __restrict__ b3,
    float* __restrict__ out)
{
    extern __shared__ float sm[];
    float*  w3s   = sm;
    float4* boxes = (float4*)(sm + W3S_FLOATS);
    float*  ss    = (float*)(boxes + PRE);
    int*    keep  = (int*)(ss + PRE);
    __shared__ int warpcnt[16];

    const int b = blockIdx.x;
    const int j = threadIdx.x;

    for (int i = j; i < 36*512; i += 512) {
        int row = i >> 9, c = i & 511;
        w3s[row*513 + c] = w3[i];
    }
    __syncthreads();

    const int   idx = g_topidx[b*PRE + j];
    const float s   = g_topscore[b*PRE + j];
    const int p = idx / 9, a = idx % 9;

    float so[4] = {0.f,0.f,0.f,0.f}, co[4] = {0.f,0.f,0.f,0.f};
    {
        const float* col = g_shared + (size_t)b * CIN * HW + p;
        const float* w0 = w3s + (a*4+0)*513;
        const float* w1r= w3s + (a*4+1)*513;
        const float* w2r= w3s + (a*4+2)*513;
        const float* w3r= w3s + (a*4+3)*513;
        for (int c = 0; c < CIN; c++) {
            float v = col[(size_t)c * HW];
            KAHAN_ADD(so[0], co[0], __fmul_rn(v, w0[c]));
            KAHAN_ADD(so[1], co[1], __fmul_rn(v, w1r[c]));
            KAHAN_ADD(so[2], co[2], __fmul_rn(v, w2r[c]));
            KAHAN_ADD(so[3], co[3], __fmul_rn(v, w3r[c]));
        }
    }
    const float o0 = __fadd_rn(__fsub_rn(so[0], co[0]), b3[a*4+0]);
    const float o1 = __fadd_rn(__fsub_rn(so[1], co[1]), b3[a*4+1]);
    const float o2 = __fadd_rn(__fsub_rn(so[2], co[2]), b3[a*4+2]);
    const float o3 = __fadd_rn(__fsub_rn(so[3], co[3]), b3[a*4+3]);

    const int ay = p / FW, ax = p % FW;
    const double cxd = (ax + 0.5) * 16.0;
    const double cyd = (ay + 0.5) * 16.0;
    const int si = a / 3, ri = a % 3;
    const double sz = (si == 0) ? 32.0 : (si == 1) ? 64.0 : 128.0;
    const double rr = (ri == 0) ? 0.5 : (ri == 1) ? 1.0 : 2.0;
    const float hf = (float)(sz * sqrt(rr));
    const float wf = (float)(sz / sqrt(rr));
    const float ax1 = (float)(cxd - (double)wf * 0.5);
    const float ay1 = (float)(cyd - (double)hf * 0.5);
    const float ax2 = (float)(cxd + (double)wf * 0.5);
    const float ay2 = (float)(cyd + (double)hf * 0.5);

    const float aw = __fsub_rn(ax2, ax1), ah = __fsub_rn(ay2, ay1);
    const float acx = __fadd_rn(ax1, __fmul_rn(0.5f, aw));
    const float acy = __fadd_rn(ay1, __fmul_rn(0.5f, ah));
    const float pcx = __fadd_rn(acx, __fmul_rn(o0, aw));
    const float pcy = __fadd_rn(acy, __fmul_rn(o1, ah));
    const float pw  = __fmul_rn(aw, (float)exp((double)o2));
    const float ph  = __fmul_rn(ah, (float)exp((double)o3));
    float x1 = __fsub_rn(pcx, __fmul_rn(0.5f, pw));
    float y1 = __fsub_rn(pcy, __fmul_rn(0.5f, ph));
    float x2 = __fadd_rn(pcx, __fmul_rn(0.5f, pw));
    float y2 = __fadd_rn(pcy, __fmul_rn(0.5f, ph));
    x1 = fminf(fmaxf(x1, 0.f), IMGW);
    y1 = fminf(fmaxf(y1, 0.f), IMGH);
    x2 = fminf(fmaxf(x2, 0.f), IMGW);
    y2 = fminf(fmaxf(y2, 0.f), IMGH);

    const float wb = x2 - x1, hb = y2 - y1;
    const bool valid = (wb >= 0.001f) && (hb >= 0.001f) && (s >= 0.5f);

    boxes[j] = make_float4(x1, y1, x2, y2);
    ss[j]    = s;
    keep[j]  = valid ? 1 : 0;
    __syncthreads();

    const float4 mb = boxes[j];
    const float myarea = (mb.z - mb.x) * (mb.w - mb.y);

    for (int i = 0; i < PRE - 1; i++) {
        __syncthreads();
        if (j > i && keep[i]) {
            float4 bi = boxes[i];
            float ltx = fmaxf(bi.x, mb.x), lty = fmaxf(bi.y, mb.y);
            float rbx = fminf(bi.z, mb.z), rby = fminf(bi.w, mb.w);
            float iw = fmaxf(rbx - ltx, 0.f), ih = fmaxf(rby - lty, 0.f);
            float inter = iw * ih;
            float ai = (bi.z - bi.x) * (bi.w - bi.y);
            float iou = inter / (ai + myarea - inter + 1e-9f);
            if (iou > 0.7f) keep[j] = 0;
        }
    }
    __syncthreads();

    const int lane = j & 31, warp = j >> 5;
    unsigned int m = __ballot_sync(0xffffffffu, keep[j] != 0);
    int pre = __popc(m & ((1u << lane) - 1u));
    if (lane == 0) warpcnt[warp] = __popc(m);
    __syncthreads();
    int base = 0, total = 0;
#pragma unroll
    for (int wi = 0; wi < 16; wi++) {
        int c = warpcnt[wi];
        if (wi < warp) base += c;
        total += c;
    }
    const int rank = base + pre;

    float* ob = out + (size_t)b * POST * 4;
    float* os = out + (size_t)BATCH * POST * 4 + (size_t)b * POST;

    if (j < POST && j >= total) {
        ob[j*4+0] = 0.f; ob[j*4+1] = 0.f; ob[j*4+2] = 0.f; ob[j*4+3] = 0.f;
        os[j] = 0.f;
    }
    if (keep[j] && rank < POST) {
        ob[rank*4+0] = mb.x; ob[rank*4+1] = mb.y;
        ob[rank*4+2] = mb.z; ob[rank*4+3] = mb.w;
        os[rank] = ss[j];
    }
}

// =========================== host launcher ==============================
extern "C" void kernel_launch(void* const* d_in, const int* in_sizes, int n_in,
                              void* d_out, int out_size)
{
    const float* fm = (const float*)d_in[0];
    const float* w1 = (const float*)d_in[1];
    const float* b1 = (const float*)d_in[2];
    const float* w2 = (const float*)d_in[3];
    const float* b2 = (const float*)d_in[4];
    const float* w3 = (const float*)d_in[5];
    const float* b3 = (const float*)d_in[6];
    float* out = (float*)d_out;

    transpose_w1_kernel<<<dim3(144, 16), 256>>>(w1);

    // K1: 32oc x 128px tiles, 128 threads
    conv3x3_kernel<<<dim3((HW + BPX - 1) / BPX, CIN / BOC, BATCH), 128>>>(fm, b1);

    cls_kernel<<<dim3((HW + 255) / 256, BATCH), 256>>>(w2, b2);

    const int topk_smem = 32768*4 + 1024*4 + 1024*8;
    cudaFuncSetAttribute(topk_kernel,
                         cudaFuncAttributeMaxDynamicSharedMemorySize, topk_smem);
    topk_kernel<<<BATCH, 1024, topk_smem>>>();

    const int prop_smem = W3S_FLOATS*4 + PRE*16 + PRE*4 + PRE*4;
    cudaFuncSetAttribute(proposal_kernel,
                         cudaFuncAttributeMaxDynamicSharedMemorySize, prop_smem);
    proposal_kernel<<<BATCH, PRE, prop_smem>>>(w3, b3, out);
}

// round 7
// speedup vs baseline: 1.0487x; 1.0487x over previous
#include <cuda_runtime.h>
#include <cuda_bf16.h>
#include <math.h>

#define BATCH 16
#define CIN   512
#define FH    50
#define FW    50
#define HW    2500
#define NANCH 9
#define NTOT  (HW*NANCH)
#define PRE   512
#define POST  128
#define IMGW  800.0f
#define IMGH  800.0f
#define KB    4               // input channels per staging step

typedef unsigned long long ull;

// ---- packed f32x2 ops (per-lane IEEE rn -> bit-identical to scalar) ----
#define F2MUL(d,a,b)   asm("mul.rn.f32x2 %0,%1,%2;"    : "=l"(d) : "l"(a), "l"(b))
#define F2ADD(d,a,b)   asm("add.rn.f32x2 %0,%1,%2;"    : "=l"(d) : "l"(a), "l"(b))
#define F2SUB(d,a,b)   asm("sub.rn.f32x2 %0,%1,%2;"    : "=l"(d) : "l"(a), "l"(b))
#define F2FMA(d,a,b,c) asm("fma.rn.f32x2 %0,%1,%2,%3;" : "=l"(d) : "l"(a), "l"(b), "l"(c))
#define F2UNPACK(lo,hi,v) asm("mov.b64 {%0,%1},%2;" : "=f"(lo), "=f"(hi) : "l"(v))

// packed Kahan (same op sequence as scalar KAHAN_ADD, per lane)
#define K2ADD(s,c,p) do { ull _y,_t,_u;                \
    F2SUB(_y,(p),(c)); F2ADD(_t,(s),_y);               \
    F2SUB(_u,_t,(s));  F2SUB((c),_u,_y); (s)=_t;       \
} while (0)

// scalar Kahan (K2/K4, unchanged)
#define KAHAN_ADD(s, c, p) do {                        \
    float _y = __fsub_rn((p), (c));                    \
    float _t = __fadd_rn((s), _y);                     \
    (c) = __fsub_rn(__fsub_rn(_t, (s)), _y);           \
    (s) = _t;                                          \
} while (0)

// ---------------- device scratch ----------------
__device__ float g_shared[(size_t)BATCH*CIN*HW];
__device__ float g_scores[(size_t)BATCH*NTOT];
__device__ int   g_topidx[BATCH*PRE];
__device__ float g_topscore[BATCH*PRE];
__device__ float2 g_w1p[(size_t)4608*512];    // transposed + duplicated (w,w)

// ========= K0: transpose w1 [oc][4608] -> [4608][oc] as (w,w) pairs =====
__global__ __launch_bounds__(256) void transpose_w1_kernel(
    const float* __restrict__ w1)
{
    __shared__ float t[32][33];
    const int r0 = blockIdx.x * 32;
    const int c0 = blockIdx.y * 32;
    const int tx = threadIdx.x & 31, ty = threadIdx.x >> 5;
#pragma unroll
    for (int i = 0; i < 4; i++)
        t[ty + i*8][tx] = w1[(size_t)(c0 + ty + i*8) * 4608 + r0 + tx];
    __syncthreads();
#pragma unroll
    for (int i = 0; i < 4; i++) {
        float w = t[tx][ty + i*8];
        g_w1p[(size_t)(r0 + ty + i*8) * 512 + c0 + tx] = make_float2(w, w);
    }
}

// ===== K1: 3x3 conv, packed f32x2, 64oc x 64px tile, 4oc x 4px/thread ===
__global__ __launch_bounds__(256, 2) void conv3x3_kernel(
    const float* __restrict__ x, const float* __restrict__ b1)
{
    __shared__ __align__(16) float2 Wp[KB*9][64];       // 18.4 KB, (w,w) pairs
    __shared__ __align__(16) float  XsC[KB][3][6*FW];   // 14.4 KB, 3 dx-shifts

    const int bidx = blockIdx.z;
    const int oc0  = blockIdx.y * 64;
    const int p0   = blockIdx.x * 64;
    const int tid  = threadIdx.x;
    const int tx   = tid & 15;      // 16 pixel groups (4 px each = 2 pairs)
    const int ty   = tid >> 4;      // 16 oc groups (4 oc each)

    const int r0    = p0 / FW - 1;            // first staged tap row
    const int pbase = p0 + tx * 4;            // even -> 8B-aligned pairs
    const int Lb    = pbase - FW * r0 - FW;   // linear idx for dy=-1

    ull acc[4][2], cmp[4][2];                 // [oc i][pixel-pair]
#pragma unroll
    for (int i = 0; i < 4; i++)
#pragma unroll
        for (int q = 0; q < 2; q++) { acc[i][q] = 0ULL; cmp[i][q] = 0ULL; }

    const float* xb = x + (size_t)bidx * CIN * HW;

    for (int ic0 = 0; ic0 < CIN; ic0 += KB) {
        // stage weights: KB*9 rows x 64 oc float2 = 1152 float4
        for (int j = tid; j < KB*9*32; j += 256) {
            int row = j >> 5;
            int o2  = (j & 31) << 1;
            *(float4*)&Wp[row][o2] =
                *(const float4*)&g_w1p[(size_t)(ic0*9 + row) * 512 + oc0 + o2];
        }
        // stage x: 3 dx-shifted linear copies, rows r0..r0+5, zero-padded
        for (int j = tid; j < KB*3*300; j += 256) {
            int k  = j / 900;
            int r  = j % 900;
            int s  = r / 300;
            int li = r % 300;
            int ri = r0 + li / FW;
            int cc = li % FW + s - 1;
            XsC[k][s][li] = (ri >= 0 && ri < FH && cc >= 0 && cc < FW)
                    ? xb[(size_t)(ic0 + k) * HW + ri*FW + cc] : 0.f;
        }
        __syncthreads();

#pragma unroll
        for (int k = 0; k < KB; k++) {
            // x pairs for both pixel-pairs: 18 aligned LDS.64
            ull xq[2][9];
#pragma unroll
            for (int q = 0; q < 2; q++) {
                const int off = Lb + q*2;
#pragma unroll
                for (int t = 0; t < 9; t++)
                    xq[q][t] = *(const ull*)&XsC[k][t % 3][off + (t/3)*FW];
            }
#pragma unroll
            for (int i = 0; i < 4; i++) {
                // prepacked (w,w) weight pairs: 9 broadcast LDS.64
                ull wp[9];
#pragma unroll
                for (int t = 0; t < 9; t++)
                    wp[t] = *(const ull*)&Wp[k*9 + t][ty*4 + i];
#pragma unroll
                for (int q = 0; q < 2; q++) {
                    ull d0, d1, d2, d;
                    F2MUL(d0, wp[0], xq[q][0]);
                    F2FMA(d0, wp[1], xq[q][1], d0);
                    F2FMA(d0, wp[2], xq[q][2], d0);
                    F2MUL(d1, wp[3], xq[q][3]);
                    F2FMA(d1, wp[4], xq[q][4], d1);
                    F2FMA(d1, wp[5], xq[q][5], d1);
                    F2MUL(d2, wp[6], xq[q][6]);
                    F2FMA(d2, wp[7], xq[q][7], d2);
                    F2FMA(d2, wp[8], xq[q][8], d2);
                    F2ADD(d, d0, d1);
                    F2ADD(d, d, d2);
                    K2ADD(acc[i][q], cmp[i][q], d);
                }
            }
        }
        __syncthreads();
    }

    // epilogue: r = acc - cmp (packed), unpack, +bias, relu, store
#pragma unroll
    for (int i = 0; i < 4; i++) {
        const int oc = oc0 + ty*4 + i;
        const float bias = b1[oc];
        float* op = g_shared + ((size_t)bidx*CIN + oc)*HW;
#pragma unroll
        for (int q = 0; q < 2; q++) {
            ull r;
            F2SUB(r, acc[i][q], cmp[i][q]);
            float lo, hi;
            F2UNPACK(lo, hi, r);
            int pA = pbase + q*2, pB = pA + 1;
            if (pA < HW) op[pA] = fmaxf(__fadd_rn(lo, bias), 0.f);
            if (pB < HW) op[pB] = fmaxf(__fadd_rn(hi, bias), 0.f);
        }
    }
}

// ================= K2: 1x1 cls conv (512->9) + sigmoid ==================
__global__ __launch_bounds__(256) void cls_kernel(
    const float* __restrict__ w2, const float* __restrict__ b2)
{
    __shared__ float w2s[9][512];
    const int b = blockIdx.y;
    const int p = blockIdx.x * 256 + threadIdx.x;
    for (int i = threadIdx.x; i < 9*512; i += 256)
        w2s[i/512][i%512] = w2[i];
    __syncthreads();
    if (p >= HW) return;

    float acc[9], cmp[9];
#pragma unroll
    for (int a = 0; a < 9; a++) { acc[a] = 0.f; cmp[a] = 0.f; }

    const float* sp = g_shared + (size_t)b * CIN * HW + p;
    for (int c = 0; c < CIN; c++) {
        float v = sp[(size_t)c * HW];
#pragma unroll
        for (int a = 0; a < 9; a++)
            KAHAN_ADD(acc[a], cmp[a], __fmul_rn(v, w2s[a][c]));
    }
    float* outp = g_scores + (size_t)b * NTOT + (size_t)p * 9;
#pragma unroll
    for (int a = 0; a < 9; a++) {
        float logit = __fadd_rn(__fsub_rn(acc[a], cmp[a]), b2[a]);
        double sg = 1.0 / (1.0 + exp(-(double)logit));
        outp[a] = (float)sg;
    }
}

// ================= K3: exact per-image top-512 (sorted) ==================
__global__ __launch_bounds__(1024) void topk_kernel()
{
    extern __shared__ unsigned char smraw[];
    unsigned int* hist = (unsigned int*)smraw;
    unsigned int* csum = hist + 32768;
    unsigned long long* cand = (unsigned long long*)(csum + 1024);
    __shared__ int s_tb, s_cntgt, s_thr, s_cnt;

    const int b = blockIdx.x, tid = threadIdx.x;
    const float* sc = g_scores + (size_t)b * NTOT;

    for (int i = tid; i < 32768; i += 1024) hist[i] = 0;
    __syncthreads();
    for (int i = tid; i < NTOT; i += 1024) {
        unsigned int bits = __float_as_uint(sc[i]);
        atomicAdd(&hist[bits >> 15], 1u);
    }
    __syncthreads();
    { unsigned int cs = 0;
#pragma unroll 4
      for (int k = 0; k < 32; k++) cs += hist[tid*32 + k];
      csum[tid] = cs; }
    __syncthreads();
    if (tid == 0) {
        unsigned int accum = 0;
        int ch = 1023;
        for (; ch > 0; ch--) { if (accum + csum[ch] >= PRE) break; accum += csum[ch]; }
        int bk = ch*32 + 31;
        for (; bk > ch*32; bk--) { if (accum + hist[bk] >= PRE) break; accum += hist[bk]; }
        s_tb = bk; s_cntgt = (int)accum;
    }
    __syncthreads();
    const int tb = s_tb, cntgt = s_cntgt;

    for (int i = tid; i < 32768; i += 1024) hist[i] = 0;
    __syncthreads();
    for (int i = tid; i < NTOT; i += 1024) {
        unsigned int bits = __float_as_uint(sc[i]);
        if ((int)(bits >> 15) == tb) atomicAdd(&hist[bits & 0x7FFF], 1u);
    }
    __syncthreads();
    { unsigned int cs = 0;
#pragma unroll 4
      for (int k = 0; k < 32; k++) cs += hist[tid*32 + k];
      csum[tid] = cs; }
    __syncthreads();
    if (tid == 0) {
        unsigned int accum = (unsigned int)cntgt;
        int ch = 1023;
        for (; ch > 0; ch--) { if (accum + csum[ch] >= PRE) break; accum += csum[ch]; }
        int bk = ch*32 + 31;
        for (; bk > ch*32; bk--) { if (accum + hist[bk] >= PRE) break; accum += hist[bk]; }
        s_thr = (tb << 15) | bk;
        s_cnt = 0;
    }
    __syncthreads();
    const unsigned int thrbits = (unsigned int)s_thr;

    for (int i = tid; i < NTOT; i += 1024) {
        unsigned int bits = __float_as_uint(sc[i]);
        if (bits >= thrbits) {
            int pos = atomicAdd(&s_cnt, 1);
            if (pos < 1024)
                cand[pos] = ((unsigned long long)bits << 32) |
                            (unsigned long long)(0xFFFFFFFFu - (unsigned int)i);
        }
    }
    __syncthreads();
    int cnt = s_cnt; if (cnt > 1024) cnt = 1024;
    if (tid >= cnt) cand[tid] = 0ULL;
    __syncthreads();

    for (int k = 2; k <= 1024; k <<= 1) {
        for (int j = k >> 1; j > 0; j >>= 1) {
            int ixj = tid ^ j;
            if (ixj > tid) {
                unsigned long long a = cand[tid], c = cand[ixj];
                bool up = ((tid & k) == 0);
                bool sw = up ? (a < c) : (a > c);
                if (sw) { cand[tid] = c; cand[ixj] = a; }
            }
            __syncthreads();
        }
    }

    if (tid < PRE) {
        unsigned long long key = cand[tid];
        unsigned int idx = 0xFFFFFFFFu - (unsigned int)(key & 0xFFFFFFFFull);
        g_topidx[b*PRE + tid]   = (int)idx;
        g_topscore[b*PRE + tid] = __uint_as_float((unsigned int)(key >> 32));
    }
}

// ====== K4: offsets@selected + anchors + decode + clip + NMS + output ====
#define W3S_FLOATS (36*513)
__global__ __launch_bounds__(512) void proposal_kernel(
    const float* __restrict__ w3, const float* __restrict__ b3,
    float* __restrict__ out)
{
    extern __shared__ float sm[];
    float*  w3s   = sm;
    float4* boxes = (float4*)(sm + W3S_FLOATS);
    float*  ss    = (float*)(boxes + PRE);
    int*    keep  = (int*)(ss + PRE);
    __shared__ int warpcnt[16];

    const int b = blockIdx.x;
    const int j = threadIdx.x;

    for (int i = j; i < 36*512; i += 512) {
        int row = i >> 9, c = i & 511;
        w3s[row*513 + c] = w3[i];
    }
    __syncthreads();

    const int   idx = g_topidx[b*PRE + j];
    const float s   = g_topscore[b*PRE + j];
    const int p = idx / 9, a = idx % 9;

    float so[4] = {0.f,0.f,0.f,0.f}, co[4] = {0.f,0.f,0.f,0.f};
    {
        const float* col = g_shared + (size_t)b * CIN * HW + p;
        const float* w0 = w3s + (a*4+0)*513;
        const float* w1r= w3s + (a*4+1)*513;
        const float* w2r= w3s + (a*4+2)*513;
        const float* w3r= w3s + (a*4+3)*513;
        for (int c = 0; c < CIN; c++) {
            float v = col[(size_t)c * HW];
            KAHAN_ADD(so[0], co[0], __fmul_rn(v, w0[c]));
            KAHAN_ADD(so[1], co[1], __fmul_rn(v, w1r[c]));
            KAHAN_ADD(so[2], co[2], __fmul_rn(v, w2r[c]));
            KAHAN_ADD(so[3], co[3], __fmul_rn(v, w3r[c]));
        }
    }
    const float o0 = __fadd_rn(__fsub_rn(so[0], co[0]), b3[a*4+0]);
    const float o1 = __fadd_rn(__fsub_rn(so[1], co[1]), b3[a*4+1]);
    const float o2 = __fadd_rn(__fsub_rn(so[2], co[2]), b3[a*4+2]);
    const float o3 = __fadd_rn(__fsub_rn(so[3], co[3]), b3[a*4+3]);

    const int ay = p / FW, ax = p % FW;
    const double cxd = (ax + 0.5) * 16.0;
    const double cyd = (ay + 0.5) * 16.0;
    const int si = a / 3, ri = a % 3;
    const double sz = (si == 0) ? 32.0 : (si == 1) ? 64.0 : 128.0;
    const double rr = (ri == 0) ? 0.5 : (ri == 1) ? 1.0 : 2.0;
    const float hf = (float)(sz * sqrt(rr));
    const float wf = (float)(sz / sqrt(rr));
    const float ax1 = (float)(cxd - (double)wf * 0.5);
    const float ay1 = (float)(cyd - (double)hf * 0.5);
    const float ax2 = (float)(cxd + (double)wf * 0.5);
    const float ay2 = (float)(cyd + (double)hf * 0.5);

    const float aw = __fsub_rn(ax2, ax1), ah = __fsub_rn(ay2, ay1);
    const float acx = __fadd_rn(ax1, __fmul_rn(0.5f, aw));
    const float acy = __fadd_rn(ay1, __fmul_rn(0.5f, ah));
    const float pcx = __fadd_rn(acx, __fmul_rn(o0, aw));
    const float pcy = __fadd_rn(acy, __fmul_rn(o1, ah));
    const float pw  = __fmul_rn(aw, (float)exp((double)o2));
    const float ph  = __fmul_rn(ah, (float)exp((double)o3));
    float x1 = __fsub_rn(pcx, __fmul_rn(0.5f, pw));
    float y1 = __fsub_rn(pcy, __fmul_rn(0.5f, ph));
    float x2 = __fadd_rn(pcx, __fmul_rn(0.5f, pw));
    float y2 = __fadd_rn(pcy, __fmul_rn(0.5f, ph));
    x1 = fminf(fmaxf(x1, 0.f), IMGW);
    y1 = fminf(fmaxf(y1, 0.f), IMGH);
    x2 = fminf(fmaxf(x2, 0.f), IMGW);
    y2 = fminf(fmaxf(y2, 0.f), IMGH);

    const float wb = x2 - x1, hb = y2 - y1;
    const bool valid = (wb >= 0.001f) && (hb >= 0.001f) && (s >= 0.5f);

    boxes[j] = make_float4(x1, y1, x2, y2);
    ss[j]    = s;
    keep[j]  = valid ? 1 : 0;
    __syncthreads();

    const float4 mb = boxes[j];
    const float myarea = (mb.z - mb.x) * (mb.w - mb.y);

    for (int i = 0; i < PRE - 1; i++) {
        __syncthreads();
        if (j > i && keep[i]) {
            float4 bi = boxes[i];
            float ltx = fmaxf(bi.x, mb.x), lty = fmaxf(bi.y, mb.y);
            float rbx = fminf(bi.z, mb.z), rby = fminf(bi.w, mb.w);
            float iw = fmaxf(rbx - ltx, 0.f), ih = fmaxf(rby - lty, 0.f);
            float inter = iw * ih;
            float ai = (bi.z - bi.x) * (bi.w - bi.y);
            float iou = inter / (ai + myarea - inter + 1e-9f);
            if (iou > 0.7f) keep[j] = 0;
        }
    }
    __syncthreads();

    const int lane = j & 31, warp = j >> 5;
    unsigned int m = __ballot_sync(0xffffffffu, keep[j] != 0);
    int pre = __popc(m & ((1u << lane) - 1u));
    if (lane == 0) warpcnt[warp] = __popc(m);
    __syncthreads();
    int base = 0, total = 0;
#pragma unroll
    for (int wi = 0; wi < 16; wi++) {
        int c = warpcnt[wi];
        if (wi < warp) base += c;
        total += c;
    }
    const int rank = base + pre;

    float* ob = out + (size_t)b * POST * 4;
    float* os = out + (size_t)BATCH * POST * 4 + (size_t)b * POST;

    if (j < POST && j >= total) {
        ob[j*4+0] = 0.f; ob[j*4+1] = 0.f; ob[j*4+2] = 0.f; ob[j*4+3] = 0.f;
        os[j] = 0.f;
    }
    if (keep[j] && rank < POST) {
        ob[rank*4+0] = mb.x; ob[rank*4+1] = mb.y;
        ob[rank*4+2] = mb.z; ob[rank*4+3] = mb.w;
        os[rank] = ss[j];
    }
}

// =========================== host launcher ==============================
extern "C" void kernel_launch(void* const* d_in, const int* in_sizes, int n_in,
                              void* d_out, int out_size)
{
    const float* fm = (const float*)d_in[0];
    const float* w1 = (const float*)d_in[1];
    const float* b1 = (const float*)d_in[2];
    const float* w2 = (const float*)d_in[3];
    const float* b2 = (const float*)d_in[4];
    const float* w3 = (const float*)d_in[5];
    const float* b3 = (const float*)d_in[6];
    float* out = (float*)d_out;

    transpose_w1_kernel<<<dim3(144, 16), 256>>>(w1);

    // K1: 64oc x 64px tiles, 256 threads, packed f32x2
    conv3x3_kernel<<<dim3(40, 8, BATCH), 256>>>(fm, b1);

    cls_kernel<<<dim3((HW + 255) / 256, BATCH), 256>>>(w2, b2);

    const int topk_smem = 32768*4 + 1024*4 + 1024*8;
    cudaFuncSetAttribute(topk_kernel,
                         cudaFuncAttributeMaxDynamicSharedMemorySize, topk_smem);
    topk_kernel<<<BATCH, 1024, topk_smem>>>();

    const int prop_smem = W3S_FLOATS*4 + PRE*16 + PRE*4 + PRE*4;
    cudaFuncSetAttribute(proposal_kernel,
                         cudaFuncAttributeMaxDynamicSharedMemorySize, prop_smem);
    proposal_kernel<<<BATCH, PRE, prop_smem>>>(w3, b3, out);
}

// round 8
// speedup vs baseline: 1.3262x; 1.2646x over previous
#include <cuda_runtime.h>
#include <cuda_bf16.h>
#include <math.h>

#define BATCH 16
#define CIN   512
#define FH    50
#define FW    50
#define HW    2500
#define NANCH 9
#define NTOT  (HW*NANCH)
#define PRE   512
#define POST  128
#define IMGW  800.0f
#define IMGH  800.0f
#define KB    4               // input channels per staging step = Kahan block

// Kahan compensated accumulation, contraction-proof via intrinsics.
#define KAHAN_ADD(s, c, p) do {                        \
    float _y = __fsub_rn((p), (c));                    \
    float _t = __fadd_rn((s), _y);                     \
    (c) = __fsub_rn(__fsub_rn(_t, (s)), _y);           \
    (s) = _t;                                          \
} while (0)

#define COMP(v,i) ((i)==0?(v).x:((i)==1?(v).y:((i)==2?(v).z:(v).w)))

// ---------------- device scratch ----------------
__device__ float g_shared[(size_t)BATCH*CIN*HW];
__device__ float g_scores[(size_t)BATCH*NTOT];
__device__ int   g_topidx[BATCH*PRE];
__device__ float g_topscore[BATCH*PRE];
__device__ float g_w1t[4608*512];                  // w1 transposed: [ic*9+t][oc]

// ================= K0: transpose w1 [oc][4608] -> [4608][oc] ============
__global__ __launch_bounds__(256) void transpose_w1_kernel(
    const float* __restrict__ w1)
{
    __shared__ float t[32][33];
    const int r0 = blockIdx.x * 32;
    const int c0 = blockIdx.y * 32;
    const int tx = threadIdx.x & 31, ty = threadIdx.x >> 5;
#pragma unroll
    for (int i = 0; i < 4; i++)
        t[ty + i*8][tx] = w1[(size_t)(c0 + ty + i*8) * 4608 + r0 + tx];
    __syncthreads();
#pragma unroll
    for (int i = 0; i < 4; i++)
        g_w1t[(size_t)(r0 + ty + i*8) * 512 + c0 + tx] = t[tx][ty + i*8];
}

// ================= K1: 3x3 conv (512->512) + bias + ReLU =================
// 4-ic blocked compensation: one 36-term FFMA chain per (oc,px) per staging
// block, then a single Kahan add. 1.11 ops/MAC, est. rel-err ~7e-7.
__global__ __launch_bounds__(256, 2) void conv3x3_kernel(
    const float* __restrict__ x, const float* __restrict__ b1)
{
    __shared__ float Ws[KB*9][64];
    __shared__ float Xs[KB][5][52];

    const int bidx = blockIdx.z;
    const int oc0  = blockIdx.y * 64;
    const int p0   = blockIdx.x * 64;
    const int tid  = threadIdx.x;
    const int tx   = tid & 15;     // pixel group
    const int ty   = tid >> 4;     // oc group

    const int yA = p0 / FW;

    int  pj[4], rj[4], cj[4];
    bool inb[4];
#pragma unroll
    for (int jj = 0; jj < 4; jj++) {
        int p = p0 + tx*4 + jj;
        pj[jj] = p;
        int py = p / FW, pxx = p % FW;
        rj[jj] = py - yA + 1;
        cj[jj] = pxx + 1;
        inb[jj] = (p < HW);
    }

    float acc[4][4], cmp[4][4];
#pragma unroll
    for (int i = 0; i < 4; i++)
#pragma unroll
        for (int j = 0; j < 4; j++) { acc[i][j] = 0.f; cmp[i][j] = 0.f; }

    const float* xb = x + (size_t)bidx * CIN * HW;

    for (int ic0 = 0; ic0 < CIN; ic0 += KB) {
        // stage weights (coalesced float4 from transposed layout)
        for (int i = tid; i < KB*9*16; i += 256) {
            int row = i >> 4;
            int o4  = (i & 15) << 2;
            *(float4*)&Ws[row][o4] =
                *(const float4*)&g_w1t[(size_t)(ic0*9 + row) * 512 + oc0 + o4];
        }
        // stage inputs: KB patches of 5x52, zero-padded
        for (int i = tid; i < KB*260; i += 256) {
            int k  = i / 260;
            int rr = (i % 260) / 52, cc = i % 52;
            int yy = yA - 1 + rr, xx = cc - 1;
            Xs[k][rr][cc] = (yy >= 0 && yy < FH && xx >= 0 && xx < FW)
                    ? xb[(size_t)(ic0 + k) * HW + yy*FW + xx] : 0.f;
        }
        __syncthreads();

        // d[i][jj]: 36-term chain across KB ics x 9 taps
        float d[4][4];
#pragma unroll
        for (int k = 0; k < KB; k++) {
            float4 wv[9];
#pragma unroll
            for (int t = 0; t < 9; t++)
                wv[t] = *(const float4*)&Ws[k*9 + t][ty*4];

#pragma unroll
            for (int jj = 0; jj < 4; jj++) {
                float xv[9];
#pragma unroll
                for (int t = 0; t < 9; t++)
                    xv[t] = Xs[k][rj[jj] + t/3 - 1][cj[jj] + t%3 - 1];

#pragma unroll
                for (int i = 0; i < 4; i++) {
                    if (k == 0) {
                        d[i][jj] = __fmul_rn(COMP(wv[0],i), xv[0]);
                    } else {
                        d[i][jj] = __fmaf_rn(COMP(wv[0],i), xv[0], d[i][jj]);
                    }
#pragma unroll
                    for (int t = 1; t < 9; t++)
                        d[i][jj] = __fmaf_rn(COMP(wv[t],i), xv[t], d[i][jj]);
                }
            }
        }
#pragma unroll
        for (int i = 0; i < 4; i++)
#pragma unroll
            for (int jj = 0; jj < 4; jj++)
                KAHAN_ADD(acc[i][jj], cmp[i][jj], d[i][jj]);
        __syncthreads();
    }

#pragma unroll
    for (int ii = 0; ii < 4; ii++) {
        int oc = oc0 + ty*4 + ii;
        float bias = b1[oc];
#pragma unroll
        for (int jj = 0; jj < 4; jj++) {
            if (inb[jj]) {
                float r = __fsub_rn(acc[ii][jj], cmp[ii][jj]);
                float v = __fadd_rn(r, bias);
                g_shared[((size_t)bidx*CIN + oc)*HW + pj[jj]] = fmaxf(v, 0.f);
            }
        }
    }
}

// ================= K2: 1x1 cls conv (512->9) + sigmoid ==================
__global__ __launch_bounds__(256) void cls_kernel(
    const float* __restrict__ w2, const float* __restrict__ b2)
{
    __shared__ float w2s[9][512];
    const int b = blockIdx.y;
    const int p = blockIdx.x * 256 + threadIdx.x;
    for (int i = threadIdx.x; i < 9*512; i += 256)
        w2s[i/512][i%512] = w2[i];
    __syncthreads();
    if (p >= HW) return;

    float acc[9], cmp[9];
#pragma unroll
    for (int a = 0; a < 9; a++) { acc[a] = 0.f; cmp[a] = 0.f; }

    const float* sp = g_shared + (size_t)b * CIN * HW + p;
    for (int c = 0; c < CIN; c++) {
        float v = sp[(size_t)c * HW];
#pragma unroll
        for (int a = 0; a < 9; a++)
            KAHAN_ADD(acc[a], cmp[a], __fmul_rn(v, w2s[a][c]));
    }
    float* outp = g_scores + (size_t)b * NTOT + (size_t)p * 9;
#pragma unroll
    for (int a = 0; a < 9; a++) {
        float logit = __fadd_rn(__fsub_rn(acc[a], cmp[a]), b2[a]);
        double sg = 1.0 / (1.0 + exp(-(double)logit));
        outp[a] = (float)sg;
    }
}

// ================= K3: exact per-image top-512 (sorted) ==================
__global__ __launch_bounds__(1024) void topk_kernel()
{
    extern __shared__ unsigned char smraw[];
    unsigned int* hist = (unsigned int*)smraw;
    unsigned int* csum = hist + 32768;
    unsigned long long* cand = (unsigned long long*)(csum + 1024);
    __shared__ int s_tb, s_cntgt, s_thr, s_cnt;

    const int b = blockIdx.x, tid = threadIdx.x;
    const float* sc = g_scores + (size_t)b * NTOT;

    for (int i = tid; i < 32768; i += 1024) hist[i] = 0;
    __syncthreads();
    for (int i = tid; i < NTOT; i += 1024) {
        unsigned int bits = __float_as_uint(sc[i]);
        atomicAdd(&hist[bits >> 15], 1u);
    }
    __syncthreads();
    { unsigned int cs = 0;
#pragma unroll 4
      for (int k = 0; k < 32; k++) cs += hist[tid*32 + k];
      csum[tid] = cs; }
    __syncthreads();
    if (tid == 0) {
        unsigned int accum = 0;
        int ch = 1023;
        for (; ch > 0; ch--) { if (accum + csum[ch] >= PRE) break; accum += csum[ch]; }
        int bk = ch*32 + 31;
        for (; bk > ch*32; bk--) { if (accum + hist[bk] >= PRE) break; accum += hist[bk]; }
        s_tb = bk; s_cntgt = (int)accum;
    }
    __syncthreads();
    const int tb = s_tb, cntgt = s_cntgt;

    for (int i = tid; i < 32768; i += 1024) hist[i] = 0;
    __syncthreads();
    for (int i = tid; i < NTOT; i += 1024) {
        unsigned int bits = __float_as_uint(sc[i]);
        if ((int)(bits >> 15) == tb) atomicAdd(&hist[bits & 0x7FFF], 1u);
    }
    __syncthreads();
    { unsigned int cs = 0;
#pragma unroll 4
      for (int k = 0; k < 32; k++) cs += hist[tid*32 + k];
      csum[tid] = cs; }
    __syncthreads();
    if (tid == 0) {
        unsigned int accum = (unsigned int)cntgt;
        int ch = 1023;
        for (; ch > 0; ch--) { if (accum + csum[ch] >= PRE) break; accum += csum[ch]; }
        int bk = ch*32 + 31;
        for (; bk > ch*32; bk--) { if (accum + hist[bk] >= PRE) break; accum += hist[bk]; }
        s_thr = (tb << 15) | bk;
        s_cnt = 0;
    }
    __syncthreads();
    const unsigned int thrbits = (unsigned int)s_thr;

    for (int i = tid; i < NTOT; i += 1024) {
        unsigned int bits = __float_as_uint(sc[i]);
        if (bits >= thrbits) {
            int pos = atomicAdd(&s_cnt, 1);
            if (pos < 1024)
                cand[pos] = ((unsigned long long)bits << 32) |
                            (unsigned long long)(0xFFFFFFFFu - (unsigned int)i);
        }
    }
    __syncthreads();
    int cnt = s_cnt; if (cnt > 1024) cnt = 1024;
    if (tid >= cnt) cand[tid] = 0ULL;
    __syncthreads();

    for (int k = 2; k <= 1024; k <<= 1) {
        for (int j = k >> 1; j > 0; j >>= 1) {
            int ixj = tid ^ j;
            if (ixj > tid) {
                unsigned long long a = cand[tid], c = cand[ixj];
                bool up = ((tid & k) == 0);
                bool sw = up ? (a < c) : (a > c);
                if (sw) { cand[tid] = c; cand[ixj] = a; }
            }
            __syncthreads();
        }
    }

    if (tid < PRE) {
        unsigned long long key = cand[tid];
        unsigned int idx = 0xFFFFFFFFu - (unsigned int)(key & 0xFFFFFFFFull);
        g_topidx[b*PRE + tid]   = (int)idx;
        g_topscore[b*PRE + tid] = __uint_as_float((unsigned int)(key >> 32));
    }
}

// ====== K4: offsets@selected + anchors + decode + clip + NMS + output ====
#define W3S_FLOATS (36*513)
__global__ __launch_bounds__(512) void proposal_kernel(
    const float* __restrict__ w3, const float* __restrict__ b3,
    float* __restrict__ out)
{
    extern __shared__ float sm[];
    float*  w3s   = sm;
    float4* boxes = (float4*)(sm + W3S_FLOATS);
    float*  ss    = (float*)(boxes + PRE);
    int*    keep  = (int*)(ss + PRE);
    __shared__ int warpcnt[16];

    const int b = blockIdx.x;
    const int j = threadIdx.x;

    for (int i = j; i < 36*512; i += 512) {
        int row = i >> 9, c = i & 511;
        w3s[row*513 + c] = w3[i];
    }
    __syncthreads();

    const int   idx = g_topidx[b*PRE + j];
    const float s   = g_topscore[b*PRE + j];
    const int p = idx / 9, a = idx % 9;

    float so[4] = {0.f,0.f,0.f,0.f}, co[4] = {0.f,0.f,0.f,0.f};
    {
        const float* col = g_shared + (size_t)b * CIN * HW + p;
        const float* w0 = w3s + (a*4+0)*513;
        const float* w1r= w3s + (a*4+1)*513;
        const float* w2r= w3s + (a*4+2)*513;
        const float* w3r= w3s + (a*4+3)*513;
        for (int c = 0; c < CIN; c++) {
            float v = col[(size_t)c * HW];
            KAHAN_ADD(so[0], co[0], __fmul_rn(v, w0[c]));
            KAHAN_ADD(so[1], co[1], __fmul_rn(v, w1r[c]));
            KAHAN_ADD(so[2], co[2], __fmul_rn(v, w2r[c]));
            KAHAN_ADD(so[3], co[3], __fmul_rn(v, w3r[c]));
        }
    }
    const float o0 = __fadd_rn(__fsub_rn(so[0], co[0]), b3[a*4+0]);
    const float o1 = __fadd_rn(__fsub_rn(so[1], co[1]), b3[a*4+1]);
    const float o2 = __fadd_rn(__fsub_rn(so[2], co[2]), b3[a*4+2]);
    const float o3 = __fadd_rn(__fsub_rn(so[3], co[3]), b3[a*4+3]);

    const int ay = p / FW, ax = p % FW;
    const double cxd = (ax + 0.5) * 16.0;
    const double cyd = (ay + 0.5) * 16.0;
    const int si = a / 3, ri = a % 3;
    const double sz = (si == 0) ? 32.0 : (si == 1) ? 64.0 : 128.0;
    const double rr = (ri == 0) ? 0.5 : (ri == 1) ? 1.0 : 2.0;
    const float hf = (float)(sz * sqrt(rr));
    const float wf = (float)(sz / sqrt(rr));
    const float ax1 = (float)(cxd - (double)wf * 0.5);
    const float ay1 = (float)(cyd - (double)hf * 0.5);
    const float ax2 = (float)(cxd + (double)wf * 0.5);
    const float ay2 = (float)(cyd + (double)hf * 0.5);

    const float aw = __fsub_rn(ax2, ax1), ah = __fsub_rn(ay2, ay1);
    const float acx = __fadd_rn(ax1, __fmul_rn(0.5f, aw));
    const float acy = __fadd_rn(ay1, __fmul_rn(0.5f, ah));
    const float pcx = __fadd_rn(acx, __fmul_rn(o0, aw));
    const float pcy = __fadd_rn(acy, __fmul_rn(o1, ah));
    const float pw  = __fmul_rn(aw, (float)exp((double)o2));
    const float ph  = __fmul_rn(ah, (float)exp((double)o3));
    float x1 = __fsub_rn(pcx, __fmul_rn(0.5f, pw));
    float y1 = __fsub_rn(pcy, __fmul_rn(0.5f, ph));
    float x2 = __fadd_rn(pcx, __fmul_rn(0.5f, pw));
    float y2 = __fadd_rn(pcy, __fmul_rn(0.5f, ph));
    x1 = fminf(fmaxf(x1, 0.f), IMGW);
    y1 = fminf(fmaxf(y1, 0.f), IMGH);
    x2 = fminf(fmaxf(x2, 0.f), IMGW);
    y2 = fminf(fmaxf(y2, 0.f), IMGH);

    const float wb = x2 - x1, hb = y2 - y1;
    const bool valid = (wb >= 0.001f) && (hb >= 0.001f) && (s >= 0.5f);

    boxes[j] = make_float4(x1, y1, x2, y2);
    ss[j]    = s;
    keep[j]  = valid ? 1 : 0;
    __syncthreads();

    const float4 mb = boxes[j];
    const float myarea = (mb.z - mb.x) * (mb.w - mb.y);

    for (int i = 0; i < PRE - 1; i++) {
        __syncthreads();
        if (j > i && keep[i]) {
            float4 bi = boxes[i];
            float ltx = fmaxf(bi.x, mb.x), lty = fmaxf(bi.y, mb.y);
            float rbx = fminf(bi.z, mb.z), rby = fminf(bi.w, mb.w);
            float iw = fmaxf(rbx - ltx, 0.f), ih = fmaxf(rby - lty, 0.f);
            float inter = iw * ih;
            float ai = (bi.z - bi.x) * (bi.w - bi.y);
            float iou = inter / (ai + myarea - inter + 1e-9f);
            if (iou > 0.7f) keep[j] = 0;
        }
    }
    __syncthreads();

    const int lane = j & 31, warp = j >> 5;
    unsigned int m = __ballot_sync(0xffffffffu, keep[j] != 0);
    int pre = __popc(m & ((1u << lane) - 1u));
    if (lane == 0) warpcnt[warp] = __popc(m);
    __syncthreads();
    int base = 0, total = 0;
#pragma unroll
    for (int wi = 0; wi < 16; wi++) {
        int c = warpcnt[wi];
        if (wi < warp) base += c;
        total += c;
    }
    const int rank = base + pre;

    float* ob = out + (size_t)b * POST * 4;
    float* os = out + (size_t)BATCH * POST * 4 + (size_t)b * POST;

    if (j < POST && j >= total) {
        ob[j*4+0] = 0.f; ob[j*4+1] = 0.f; ob[j*4+2] = 0.f; ob[j*4+3] = 0.f;
        os[j] = 0.f;
    }
    if (keep[j] && rank < POST) {
        ob[rank*4+0] = mb.x; ob[rank*4+1] = mb.y;
        ob[rank*4+2] = mb.z; ob[rank*4+3] = mb.w;
        os[rank] = ss[j];
    }
}

// =========================== host launcher ==============================
extern "C" void kernel_launch(void* const* d_in, const int* in_sizes, int n_in,
                              void* d_out, int out_size)
{
    const float* fm = (const float*)d_in[0];
    const float* w1 = (const float*)d_in[1];
    const float* b1 = (const float*)d_in[2];
    const float* w2 = (const float*)d_in[3];
    const float* b2 = (const float*)d_in[4];
    const float* w3 = (const float*)d_in[5];
    const float* b3 = (const float*)d_in[6];
    float* out = (float*)d_out;

    transpose_w1_kernel<<<dim3(144, 16), 256>>>(w1);

    conv3x3_kernel<<<dim3(40, 8, BATCH), 256>>>(fm, b1);

    cls_kernel<<<dim3((HW + 255) / 256, BATCH), 256>>>(w2, b2);

    const int topk_smem = 32768*4 + 1024*4 + 1024*8;
    cudaFuncSetAttribute(topk_kernel,
                         cudaFuncAttributeMaxDynamicSharedMemorySize, topk_smem);
    topk_kernel<<<BATCH, 1024, topk_smem>>>();

    const int prop_smem = W3S_FLOATS*4 + PRE*16 + PRE*4 + PRE*4;
    cudaFuncSetAttribute(proposal_kernel,
                         cudaFuncAttributeMaxDynamicSharedMemorySize, prop_smem);
    proposal_kernel<<<BATCH, PRE, prop_smem>>>(w3, b3, out);
}

// round 9
// speedup vs baseline: 1.3377x; 1.0087x over previous
#include <cuda_runtime.h>
#include <cuda_bf16.h>
#include <math.h>

#define BATCH 16
#define CIN   512
#define FH    50
#define FW    50
#define HW    2500
#define NANCH 9
#define NTOT  (HW*NANCH)
#define PRE   512
#define POST  128
#define IMGW  800.0f
#define IMGH  800.0f
#define KB    4               // input channels per staging step = Kahan block

// Kahan compensated accumulation, contraction-proof via intrinsics.
#define KAHAN_ADD(s, c, p) do {                        \
    float _y = __fsub_rn((p), (c));                    \
    float _t = __fadd_rn((s), _y);                     \
    (c) = __fsub_rn(__fsub_rn(_t, (s)), _y);           \
    (s) = _t;                                          \
} while (0)

#define COMP(v,i) ((i)==0?(v).x:((i)==1?(v).y:((i)==2?(v).z:(v).w)))

// ---------------- device scratch ----------------
__device__ float g_shared[(size_t)BATCH*CIN*HW];
__device__ float g_scores[(size_t)BATCH*NTOT];
__device__ int   g_topidx[BATCH*PRE];
__device__ float g_topscore[BATCH*PRE];
__device__ float g_w1t[4608*512];                  // w1 transposed: [ic*9+t][oc]

// ================= K0: transpose w1 [oc][4608] -> [4608][oc] ============
__global__ __launch_bounds__(256) void transpose_w1_kernel(
    const float* __restrict__ w1)
{
    __shared__ float t[32][33];
    const int r0 = blockIdx.x * 32;
    const int c0 = blockIdx.y * 32;
    const int tx = threadIdx.x & 31, ty = threadIdx.x >> 5;
#pragma unroll
    for (int i = 0; i < 4; i++)
        t[ty + i*8][tx] = w1[(size_t)(c0 + ty + i*8) * 4608 + r0 + tx];
    __syncthreads();
#pragma unroll
    for (int i = 0; i < 4; i++)
        g_w1t[(size_t)(r0 + ty + i*8) * 512 + c0 + tx] = t[tx][ty + i*8];
}

// ================= K1: 3x3 conv (512->512) + bias + ReLU =================
// 4-ic blocked compensation: one 36-term FFMA chain per (oc,px) per staging
// block, then a single Kahan add. 1.11 ops/MAC, est. rel-err ~7e-7.
__global__ __launch_bounds__(256, 2) void conv3x3_kernel(
    const float* __restrict__ x, const float* __restrict__ b1)
{
    __shared__ float Ws[KB*9][64];
    __shared__ float Xs[KB][5][52];

    const int bidx = blockIdx.z;
    const int oc0  = blockIdx.y * 64;
    const int p0   = blockIdx.x * 64;
    const int tid  = threadIdx.x;
    const int tx   = tid & 15;     // pixel group
    const int ty   = tid >> 4;     // oc group

    const int yA = p0 / FW;

    int  pj[4], rj[4], cj[4];
    bool inb[4];
#pragma unroll
    for (int jj = 0; jj < 4; jj++) {
        int p = p0 + tx*4 + jj;
        pj[jj] = p;
        int py = p / FW, pxx = p % FW;
        rj[jj] = py - yA + 1;
        cj[jj] = pxx + 1;
        inb[jj] = (p < HW);
    }

    float acc[4][4], cmp[4][4];
#pragma unroll
    for (int i = 0; i < 4; i++)
#pragma unroll
        for (int j = 0; j < 4; j++) { acc[i][j] = 0.f; cmp[i][j] = 0.f; }

    const float* xb = x + (size_t)bidx * CIN * HW;

    for (int ic0 = 0; ic0 < CIN; ic0 += KB) {
        // stage weights (coalesced float4 from transposed layout)
        for (int i = tid; i < KB*9*16; i += 256) {
            int row = i >> 4;
            int o4  = (i & 15) << 2;
            *(float4*)&Ws[row][o4] =
                *(const float4*)&g_w1t[(size_t)(ic0*9 + row) * 512 + oc0 + o4];
        }
        // stage inputs: KB patches of 5x52, zero-padded
        for (int i = tid; i < KB*260; i += 256) {
            int k  = i / 260;
            int rr = (i % 260) / 52, cc = i % 52;
            int yy = yA - 1 + rr, xx = cc - 1;
            Xs[k][rr][cc] = (yy >= 0 && yy < FH && xx >= 0 && xx < FW)
                    ? xb[(size_t)(ic0 + k) * HW + yy*FW + xx] : 0.f;
        }
        __syncthreads();

        // d[i][jj]: 36-term chain across KB ics x 9 taps
        float d[4][4];
#pragma unroll
        for (int k = 0; k < KB; k++) {
            float4 wv[9];
#pragma unroll
            for (int t = 0; t < 9; t++)
                wv[t] = *(const float4*)&Ws[k*9 + t][ty*4];

#pragma unroll
            for (int jj = 0; jj < 4; jj++) {
                float xv[9];
#pragma unroll
                for (int t = 0; t < 9; t++)
                    xv[t] = Xs[k][rj[jj] + t/3 - 1][cj[jj] + t%3 - 1];

#pragma unroll
                for (int i = 0; i < 4; i++) {
                    if (k == 0) {
                        d[i][jj] = __fmul_rn(COMP(wv[0],i), xv[0]);
                    } else {
                        d[i][jj] = __fmaf_rn(COMP(wv[0],i), xv[0], d[i][jj]);
                    }
#pragma unroll
                    for (int t = 1; t < 9; t++)
                        d[i][jj] = __fmaf_rn(COMP(wv[t],i), xv[t], d[i][jj]);
                }
            }
        }
#pragma unroll
        for (int i = 0; i < 4; i++)
#pragma unroll
            for (int jj = 0; jj < 4; jj++)
                KAHAN_ADD(acc[i][jj], cmp[i][jj], d[i][jj]);
        __syncthreads();
    }

#pragma unroll
    for (int ii = 0; ii < 4; ii++) {
        int oc = oc0 + ty*4 + ii;
        float bias = b1[oc];
#pragma unroll
        for (int jj = 0; jj < 4; jj++) {
            if (inb[jj]) {
                float r = __fsub_rn(acc[ii][jj], cmp[ii][jj]);
                float v = __fadd_rn(r, bias);
                g_shared[((size_t)bidx*CIN + oc)*HW + pj[jj]] = fmaxf(v, 0.f);
            }
        }
    }
}

// ================= K2: 1x1 cls conv (512->9) + sigmoid ==================
__global__ __launch_bounds__(256) void cls_kernel(
    const float* __restrict__ w2, const float* __restrict__ b2)
{
    __shared__ float w2s[9][512];
    const int b = blockIdx.y;
    const int p = blockIdx.x * 256 + threadIdx.x;
    for (int i = threadIdx.x; i < 9*512; i += 256)
        w2s[i/512][i%512] = w2[i];
    __syncthreads();
    if (p >= HW) return;

    float acc[9], cmp[9];
#pragma unroll
    for (int a = 0; a < 9; a++) { acc[a] = 0.f; cmp[a] = 0.f; }

    const float* sp = g_shared + (size_t)b * CIN * HW + p;
    for (int c = 0; c < CIN; c++) {
        float v = sp[(size_t)c * HW];
#pragma unroll
        for (int a = 0; a < 9; a++)
            KAHAN_ADD(acc[a], cmp[a], __fmul_rn(v, w2s[a][c]));
    }
    float* outp = g_scores + (size_t)b * NTOT + (size_t)p * 9;
#pragma unroll
    for (int a = 0; a < 9; a++) {
        float logit = __fadd_rn(__fsub_rn(acc[a], cmp[a]), b2[a]);
        double sg = 1.0 / (1.0 + exp(-(double)logit));
        outp[a] = (float)sg;
    }
}

// ================= K3: exact per-image top-512 (sorted) ==================
__global__ __launch_bounds__(1024) void topk_kernel()
{
    extern __shared__ unsigned char smraw[];
    unsigned int* hist = (unsigned int*)smraw;
    unsigned int* csum = hist + 32768;
    unsigned long long* cand = (unsigned long long*)(csum + 1024);
    __shared__ int s_tb, s_cntgt, s_thr, s_cnt;

    const int b = blockIdx.x, tid = threadIdx.x;
    const float* sc = g_scores + (size_t)b * NTOT;

    for (int i = tid; i < 32768; i += 1024) hist[i] = 0;
    __syncthreads();
    for (int i = tid; i < NTOT; i += 1024) {
        unsigned int bits = __float_as_uint(sc[i]);
        atomicAdd(&hist[bits >> 15], 1u);
    }
    __syncthreads();
    { unsigned int cs = 0;
#pragma unroll 4
      for (int k = 0; k < 32; k++) cs += hist[tid*32 + k];
      csum[tid] = cs; }
    __syncthreads();
    if (tid == 0) {
        unsigned int accum = 0;
        int ch = 1023;
        for (; ch > 0; ch--) { if (accum + csum[ch] >= PRE) break; accum += csum[ch]; }
        int bk = ch*32 + 31;
        for (; bk > ch*32; bk--) { if (accum + hist[bk] >= PRE) break; accum += hist[bk]; }
        s_tb = bk; s_cntgt = (int)accum;
    }
    __syncthreads();
    const int tb = s_tb, cntgt = s_cntgt;

    for (int i = tid; i < 32768; i += 1024) hist[i] = 0;
    __syncthreads();
    for (int i = tid; i < NTOT; i += 1024) {
        unsigned int bits = __float_as_uint(sc[i]);
        if ((int)(bits >> 15) == tb) atomicAdd(&hist[bits & 0x7FFF], 1u);
    }
    __syncthreads();
    { unsigned int cs = 0;
#pragma unroll 4
      for (int k = 0; k < 32; k++) cs += hist[tid*32 + k];
      csum[tid] = cs; }
    __syncthreads();
    if (tid == 0) {
        unsigned int accum = (unsigned int)cntgt;
        int ch = 1023;
        for (; ch > 0; ch--) { if (accum + csum[ch] >= PRE) break; accum += csum[ch]; }
        int bk = ch*32 + 31;
        for (; bk > ch*32; bk--) { if (accum + hist[bk] >= PRE) break; accum += hist[bk]; }
        s_thr = (tb << 15) | bk;
        s_cnt = 0;
    }
    __syncthreads();
    const unsigned int thrbits = (unsigned int)s_thr;

    for (int i = tid; i < NTOT; i += 1024) {
        unsigned int bits = __float_as_uint(sc[i]);
        if (bits >= thrbits) {
            int pos = atomicAdd(&s_cnt, 1);
            if (pos < 1024)
                cand[pos] = ((unsigned long long)bits << 32) |
                            (unsigned long long)(0xFFFFFFFFu - (unsigned int)i);
        }
    }
    __syncthreads();
    int cnt = s_cnt; if (cnt > 1024) cnt = 1024;
    if (tid >= cnt) cand[tid] = 0ULL;
    __syncthreads();

    for (int k = 2; k <= 1024; k <<= 1) {
        for (int j = k >> 1; j > 0; j >>= 1) {
            int ixj = tid ^ j;
            if (ixj > tid) {
                unsigned long long a = cand[tid], c = cand[ixj];
                bool up = ((tid & k) == 0);
                bool sw = up ? (a < c) : (a > c);
                if (sw) { cand[tid] = c; cand[ixj] = a; }
            }
            __syncthreads();
        }
    }

    if (tid < PRE) {
        unsigned long long key = cand[tid];
        unsigned int idx = 0xFFFFFFFFu - (unsigned int)(key & 0xFFFFFFFFull);
        g_topidx[b*PRE + tid]   = (int)idx;
        g_topscore[b*PRE + tid] = __uint_as_float((unsigned int)(key >> 32));
    }
}

// ====== K4: offsets@selected + anchors + decode + clip + NMS + output ====
#define W3S_FLOATS (36*513)
__global__ __launch_bounds__(512) void proposal_kernel(
    const float* __restrict__ w3, const float* __restrict__ b3,
    float* __restrict__ out)
{
    extern __shared__ float sm[];
    float*  w3s   = sm;
    float4* boxes = (float4*)(sm + W3S_FLOATS);
    float*  ss    = (float*)(boxes + PRE);
    int*    keep  = (int*)(ss + PRE);
    __shared__ int warpcnt[16];

    const int b = blockIdx.x;
    const int j = threadIdx.x;

    for (int i = j; i < 36*512; i += 512) {
        int row = i >> 9, c = i & 511;
        w3s[row*513 + c] = w3[i];
    }
    __syncthreads();

    const int   idx = g_topidx[b*PRE + j];
    const float s   = g_topscore[b*PRE + j];
    const int p = idx / 9, a = idx % 9;

    float so[4] = {0.f,0.f,0.f,0.f}, co[4] = {0.f,0.f,0.f,0.f};
    {
        const float* col = g_shared + (size_t)b * CIN * HW + p;
        const float* w0 = w3s + (a*4+0)*513;
        const float* w1r= w3s + (a*4+1)*513;
        const float* w2r= w3s + (a*4+2)*513;
        const float* w3r= w3s + (a*4+3)*513;
        for (int c = 0; c < CIN; c++) {
            float v = col[(size_t)c * HW];
            KAHAN_ADD(so[0], co[0], __fmul_rn(v, w0[c]));
            KAHAN_ADD(so[1], co[1], __fmul_rn(v, w1r[c]));
            KAHAN_ADD(so[2], co[2], __fmul_rn(v, w2r[c]));
            KAHAN_ADD(so[3], co[3], __fmul_rn(v, w3r[c]));
        }
    }
    const float o0 = __fadd_rn(__fsub_rn(so[0], co[0]), b3[a*4+0]);
    const float o1 = __fadd_rn(__fsub_rn(so[1], co[1]), b3[a*4+1]);
    const float o2 = __fadd_rn(__fsub_rn(so[2], co[2]), b3[a*4+2]);
    const float o3 = __fadd_rn(__fsub_rn(so[3], co[3]), b3[a*4+3]);

    const int ay = p / FW, ax = p % FW;
    const double cxd = (ax + 0.5) * 16.0;
    const double cyd = (ay + 0.5) * 16.0;
    const int si = a / 3, ri = a % 3;
    const double sz = (si == 0) ? 32.0 : (si == 1) ? 64.0 : 128.0;
    const double rr = (ri == 0) ? 0.5 : (ri == 1) ? 1.0 : 2.0;
    const float hf = (float)(sz * sqrt(rr));
    const float wf = (float)(sz / sqrt(rr));
    const float ax1 = (float)(cxd - (double)wf * 0.5);
    const float ay1 = (float)(cyd - (double)hf * 0.5);
    const float ax2 = (float)(cxd + (double)wf * 0.5);
    const float ay2 = (float)(cyd + (double)hf * 0.5);

    const float aw = __fsub_rn(ax2, ax1), ah = __fsub_rn(ay2, ay1);
    const float acx = __fadd_rn(ax1, __fmul_rn(0.5f, aw));
    const float acy = __fadd_rn(ay1, __fmul_rn(0.5f, ah));
    const float pcx = __fadd_rn(acx, __fmul_rn(o0, aw));
    const float pcy = __fadd_rn(acy, __fmul_rn(o1, ah));
    const float pw  = __fmul_rn(aw, (float)exp((double)o2));
    const float ph  = __fmul_rn(ah, (float)exp((double)o3));
    float x1 = __fsub_rn(pcx, __fmul_rn(0.5f, pw));
    float y1 = __fsub_rn(pcy, __fmul_rn(0.5f, ph));
    float x2 = __fadd_rn(pcx, __fmul_rn(0.5f, pw));
    float y2 = __fadd_rn(pcy, __fmul_rn(0.5f, ph));
    x1 = fminf(fmaxf(x1, 0.f), IMGW);
    y1 = fminf(fmaxf(y1, 0.f), IMGH);
    x2 = fminf(fmaxf(x2, 0.f), IMGW);
    y2 = fminf(fmaxf(y2, 0.f), IMGH);

    const float wb = x2 - x1, hb = y2 - y1;
    const bool valid = (wb >= 0.001f) && (hb >= 0.001f) && (s >= 0.5f);

    boxes[j] = make_float4(x1, y1, x2, y2);
    ss[j]    = s;
    keep[j]  = valid ? 1 : 0;
    __syncthreads();

    const float4 mb = boxes[j];
    const float myarea = (mb.z - mb.x) * (mb.w - mb.y);

    for (int i = 0; i < PRE - 1; i++) {
        __syncthreads();
        if (j > i && keep[i]) {
            float4 bi = boxes[i];
            float ltx = fmaxf(bi.x, mb.x), lty = fmaxf(bi.y, mb.y);
            float rbx = fminf(bi.z, mb.z), rby = fminf(bi.w, mb.w);
            float iw = fmaxf(rbx - ltx, 0.f), ih = fmaxf(rby - lty, 0.f);
            float inter = iw * ih;
            float ai = (bi.z - bi.x) * (bi.w - bi.y);
            float iou = inter / (ai + myarea - inter + 1e-9f);
            if (iou > 0.7f) keep[j] = 0;
        }
    }
    __syncthreads();

    const int lane = j & 31, warp = j >> 5;
    unsigned int m = __ballot_sync(0xffffffffu, keep[j] != 0);
    int pre = __popc(m & ((1u << lane) - 1u));
    if (lane == 0) warpcnt[warp] = __popc(m);
    __syncthreads();
    int base = 0, total = 0;
#pragma unroll
    for (int wi = 0; wi < 16; wi++) {
        int c = warpcnt[wi];
        if (wi < warp) base += c;
        total += c;
    }
    const int rank = base + pre;

    float* ob = out + (size_t)b * POST * 4;
    float* os = out + (size_t)BATCH * POST * 4 + (size_t)b * POST;

    if (j < POST && j >= total) {
        ob[j*4+0] = 0.f; ob[j*4+1] = 0.f; ob[j*4+2] = 0.f; ob[j*4+3] = 0.f;
        os[j] = 0.f;
    }
    if (keep[j] && rank < POST) {
        ob[rank*4+0] = mb.x; ob[rank*4+1] = mb.y;
        ob[rank*4+2] = mb.z; ob[rank*4+3] = mb.w;
        os[rank] = ss[j];
    }
}

// =========================== host launcher ==============================
extern "C" void kernel_launch(void* const* d_in, const int* in_sizes, int n_in,
                              void* d_out, int out_size)
{
    const float* fm = (const float*)d_in[0];
    const float* w1 = (const float*)d_in[1];
    const float* b1 = (const float*)d_in[2];
    const float* w2 = (const float*)d_in[3];
    const float* b2 = (const float*)d_in[4];
    const float* w3 = (const float*)d_in[5];
    const float* b3 = (const float*)d_in[6];
    float* out = (float*)d_out;

    transpose_w1_kernel<<<dim3(144, 16), 256>>>(w1);

    conv3x3_kernel<<<dim3(40, 8, BATCH), 256>>>(fm, b1);

    cls_kernel<<<dim3((HW + 255) / 256, BATCH), 256>>>(w2, b2);

    const int topk_smem = 32768*4 + 1024*4 + 1024*8;
    cudaFuncSetAttribute(topk_kernel,
                         cudaFuncAttributeMaxDynamicSharedMemorySize, topk_smem);
    topk_kernel<<<BATCH, 1024, topk_smem>>>();

    const int prop_smem = W3S_FLOATS*4 + PRE*16 + PRE*4 + PRE*4;
    cudaFuncSetAttribute(proposal_kernel,
                         cudaFuncAttributeMaxDynamicSharedMemorySize, prop_smem);
    proposal_kernel<<<BATCH, PRE, prop_smem>>>(w3, b3, out);
}

// round 12
// speedup vs baseline: 2.9358x; 2.1947x over previous
#include <cuda_runtime.h>
#include <cuda_bf16.h>
#include <math.h>
#include <stdint.h>

#define BATCH 16
#define CIN   512
#define FH    50
#define FW    50
#define HW    2500
#define NANCH 9
#define NTOT  (HW*NANCH)
#define PRE   512
#define POST  128
#define IMGW  800.0f
#define IMGH  800.0f
#define OCB   128
#define PXB   128
#define NPXT  20
#define XROWS 2688
#define XPAD  64
#define RS    72                 // padded row stride (bf16 elems)
#define TILE_B (128*RS*2)        // 18432 bytes per split tile

#define KAHAN_ADD(s, c, p) do {                        \
    float _y = __fsub_rn((p), (c));                    \
    float _t = __fadd_rn((s), _y);                     \
    (c) = __fsub_rn(__fsub_rn(_t, (s)), _y);           \
    (s) = _t;                                          \
} while (0)

__device__ float g_shared[(size_t)BATCH*CIN*HW];
__device__ float g_scores[(size_t)BATCH*NTOT];
__device__ int   g_topidx[BATCH*PRE];
__device__ float g_topscore[BATCH*PRE];
__device__ __align__(16) __nv_bfloat16 g_xsT[9][BATCH][XROWS][CIN];
__device__ __align__(16) __nv_bfloat16 g_wA[(size_t)864*8192];

__device__ __forceinline__ uint32_t smem_u32(const void* p) {
    uint32_t a;
    asm("{ .reg .u64 t; cvta.to.shared.u64 t, %1; cvt.u32.u64 %0, t; }"
        : "=r"(a) : "l"(p));
    return a;
}
__device__ __forceinline__ void split3(float v, __nv_bfloat16& s0,
                                       __nv_bfloat16& s1, __nv_bfloat16& s2) {
    s0 = __float2bfloat16_rn(v);
    float r1 = __fsub_rn(v, __bfloat162float(s0));
    s1 = __float2bfloat16_rn(r1);
    float r2 = __fsub_rn(r1, __bfloat162float(s1));
    s2 = __float2bfloat16_rn(r2);
}

__global__ __launch_bounds__(256) void zero_xsT_kernel() {
    size_t total = sizeof(g_xsT) / 16;
    uint4* p = (uint4*)g_xsT;
    uint4 z = make_uint4(0,0,0,0);
    for (size_t i = blockIdx.x * 256ull + threadIdx.x; i < total;
         i += (size_t)gridDim.x * 256ull)
        p[i] = z;
}

__global__ __launch_bounds__(256) void prep_x_kernel(const float* __restrict__ x) {
    __shared__ float Xt[32][34];
    const int p0x = blockIdx.x * 32;
    const int i0  = blockIdx.y * 32;
    const int b   = blockIdx.z;
    const int tid = threadIdx.x;
    for (int e = tid; e < 32*34; e += 256) {
        int ic = e / 34, c = e % 34;
        int p = p0x - 1 + c;
        Xt[ic][c] = (p >= 0 && p < HW)
            ? x[((size_t)b*CIN + i0 + ic)*HW + p] : 0.f;
    }
    __syncthreads();
    for (int e = tid; e < 32*32; e += 256) {
        int pl = e >> 5, ic = e & 31;
        int p = p0x + pl;
        if (p >= HW) continue;
        int xcol = p % FW;
#pragma unroll
        for (int dxi = 0; dxi < 3; dxi++) {
            int xc = xcol + dxi - 1;
            float v = (xc >= 0 && xc < FW) ? Xt[ic][pl + dxi] : 0.f;
            __nv_bfloat16 s0, s1, s2;
            split3(v, s0, s1, s2);
            g_xsT[0*3 + dxi][b][p + XPAD][i0 + ic] = s0;
            g_xsT[1*3 + dxi][b][p + XPAD][i0 + ic] = s1;
            g_xsT[2*3 + dxi][b][p + XPAD][i0 + ic] = s2;
        }
    }
}

__global__ __launch_bounds__(256) void prep_w_kernel(const float* __restrict__ w1) {
    const int id = blockIdx.x;
    const int ocblk = id & 3;
    const int icblk = (id >> 2) & 7;
    const int tmp = id >> 5;
    const int t = tmp % 9;
    const int j = tmp / 9;
    __nv_bfloat16* dst = g_wA + (size_t)id * 8192;
    for (int e = threadIdx.x; e < 8192; e += 256) {
        int r = e >> 6, c = e & 63;
        int oc = ocblk*128 + r;
        int ic = icblk*64 + c;
        float w = w1[(size_t)oc*(CIN*9) + ic*9 + t];
        __nv_bfloat16 s0, s1, s2;
        split3(w, s0, s1, s2);
        dst[r*64 + c] = (j == 0) ? s0 : (j == 1) ? s1 : s2;
    }
}

// ============ K1: conv3x3 via warp-level bf16-split mma.sync =============
// Two-level accumulation: accS zeroed every 4 chunks -> merged into accL.
__global__ __launch_bounds__(256, 1)
void conv_mma_kernel(const float* __restrict__ b1) {
    extern __shared__ unsigned char dsm[];
    const uint32_t sbA = (smem_u32(dsm) + 15u) & ~15u;
    const uint32_t sbB = sbA + 3*TILE_B;

    const int tid  = threadIdx.x;
    const int wid  = tid >> 5;
    const int lane = tid & 31;
    const int pxblk = blockIdx.x, ocblk = blockIdx.y, b = blockIdx.z;
    const int p0 = pxblk * PXB;
    const int warp_m0 = (wid & 1) * 64;
    const int warp_n0 = (wid >> 1) * 32;

    float accL[4][4][4], accS[4][4][4];
#pragma unroll
    for (int mt = 0; mt < 4; mt++)
#pragma unroll
        for (int nt = 0; nt < 4; nt++)
#pragma unroll
            for (int r = 0; r < 4; r++) { accL[mt][nt][r] = 0.f; accS[mt][nt][r] = 0.f; }

    for (int ch = 0; ch < 72; ch++) {
        const int t = ch / 8, icblk = ch % 8;
        const int dy = t / 3 - 1, dxi = t % 3;

        for (int e = tid; e < 3072; e += 256) {
            int j = e >> 10, r = (e >> 3) & 127, c8 = e & 7;
            const __nv_bfloat16* src = g_wA +
                (size_t)(((j*9 + t)*8 + icblk)*4 + ocblk) * 8192 + r*64 + c8*8;
            uint4 v = *(const uint4*)src;
            asm volatile("st.shared.v4.b32 [%0], {%1,%2,%3,%4};"
                :: "r"(sbA + (uint32_t)(j*TILE_B + r*(RS*2) + c8*16)),
                   "r"(v.x), "r"(v.y), "r"(v.z), "r"(v.w));
        }
        {
            const int rowbase = p0 + dy*FW + XPAD;
            for (int e = tid; e < 3072; e += 256) {
                int j = e >> 10, r = (e >> 3) & 127, c8 = e & 7;
                const uint4 v = *(const uint4*)
                    (&g_xsT[j*3 + dxi][b][rowbase + r][icblk*64] + c8*8);
                asm volatile("st.shared.v4.b32 [%0], {%1,%2,%3,%4};"
                    :: "r"(sbB + (uint32_t)(j*TILE_B + r*(RS*2) + c8*16)),
                       "r"(v.x), "r"(v.y), "r"(v.z), "r"(v.w));
            }
        }
        __syncthreads();

#pragma unroll
        for (int ks = 0; ks < 4; ks++) {
            const int k0 = ks * 16;
            uint32_t bf[3][4][2];
#pragma unroll
            for (int s = 0; s < 3; s++)
#pragma unroll
                for (int nt = 0; nt < 4; nt++) {
                    int row = warp_n0 + nt*8 + (lane & 7);
                    int colb = (k0 + ((lane >> 3) & 1)*8) * 2;
                    uint32_t a = sbB + s*TILE_B + row*(RS*2) + colb;
                    asm volatile(
                        "ldmatrix.sync.aligned.m8n8.x2.shared.b16 {%0,%1}, [%2];"
                        : "=r"(bf[s][nt][0]), "=r"(bf[s][nt][1]) : "r"(a));
                }
#pragma unroll
            for (int j = 0; j < 3; j++) {
                uint32_t af[4][4];
#pragma unroll
                for (int mt = 0; mt < 4; mt++) {
                    int row = warp_m0 + mt*16 + (lane & 15);
                    int colb = (k0 + (lane >> 4)*8) * 2;
                    uint32_t a = sbA + j*TILE_B + row*(RS*2) + colb;
                    asm volatile(
                        "ldmatrix.sync.aligned.m8n8.x4.shared.b16 {%0,%1,%2,%3}, [%4];"
                        : "=r"(af[mt][0]), "=r"(af[mt][1]),
                          "=r"(af[mt][2]), "=r"(af[mt][3]) : "r"(a));
                }
                const int nk = (j == 0) ? 3 : (j == 1) ? 2 : 1;
#pragma unroll
                for (int k = 0; k < 3; k++) {
                    if (k >= nk) break;
#pragma unroll
                    for (int mt = 0; mt < 4; mt++)
#pragma unroll
                        for (int nt = 0; nt < 4; nt++) {
                            asm volatile(
                                "mma.sync.aligned.m16n8k16.row.col.f32.bf16.bf16.f32 "
                                "{%0,%1,%2,%3}, {%4,%5,%6,%7}, {%8,%9}, {%0,%1,%2,%3};"
                                : "+f"(accS[mt][nt][0]), "+f"(accS[mt][nt][1]),
                                  "+f"(accS[mt][nt][2]), "+f"(accS[mt][nt][3])
                                : "r"(af[mt][0]), "r"(af[mt][1]),
                                  "r"(af[mt][2]), "r"(af[mt][3]),
                                  "r"(bf[k][nt][0]), "r"(bf[k][nt][1]));
                        }
                }
            }
        }
        // merge short accumulator into long every 4 chunks
        if ((ch & 3) == 3) {
#pragma unroll
            for (int mt = 0; mt < 4; mt++)
#pragma unroll
                for (int nt = 0; nt < 4; nt++)
#pragma unroll
                    for (int r = 0; r < 4; r++) {
                        accL[mt][nt][r] = __fadd_rn(accL[mt][nt][r],
                                                    accS[mt][nt][r]);
                        accS[mt][nt][r] = 0.f;
                    }
        }
        __syncthreads();
    }

#pragma unroll
    for (int mt = 0; mt < 4; mt++) {
#pragma unroll
        for (int half = 0; half < 2; half++) {
            int oc = ocblk*128 + warp_m0 + mt*16 + (lane >> 2) + half*8;
            float bias = b1[oc];
            float* op = g_shared + ((size_t)b*CIN + oc)*HW;
#pragma unroll
            for (int nt = 0; nt < 4; nt++) {
#pragma unroll
                for (int e = 0; e < 2; e++) {
                    int px = p0 + warp_n0 + nt*8 + (lane & 3)*2 + e;
                    if (px < HW) {
                        float v = __fadd_rn(accL[mt][nt][half*2 + e], bias);
                        op[px] = fmaxf(v, 0.f);
                    }
                }
            }
        }
    }
}

__global__ __launch_bounds__(256) void cls_kernel(
    const float* __restrict__ w2, const float* __restrict__ b2)
{
    __shared__ float w2s[9][512];
    const int b = blockIdx.y;
    const int p = blockIdx.x * 256 + threadIdx.x;
    for (int i = threadIdx.x; i < 9*512; i += 256)
        w2s[i/512][i%512] = w2[i];
    __syncthreads();
    if (p >= HW) return;
    float acc[9], cmp[9];
#pragma unroll
    for (int a = 0; a < 9; a++) { acc[a] = 0.f; cmp[a] = 0.f; }
    const float* sp = g_shared + (size_t)b * CIN * HW + p;
    for (int c = 0; c < CIN; c++) {
        float v = sp[(size_t)c * HW];
#pragma unroll
        for (int a = 0; a < 9; a++)
            KAHAN_ADD(acc[a], cmp[a], __fmul_rn(v, w2s[a][c]));
    }
    float* outp = g_scores + (size_t)b * NTOT + (size_t)p * 9;
#pragma unroll
    for (int a = 0; a < 9; a++) {
        float logit = __fadd_rn(__fsub_rn(acc[a], cmp[a]), b2[a]);
        double sg = 1.0 / (1.0 + exp(-(double)logit));
        outp[a] = (float)sg;
    }
}

__global__ __launch_bounds__(1024) void topk_kernel()
{
    extern __shared__ unsigned char smraw[];
    unsigned int* hist = (unsigned int*)smraw;
    unsigned int* csum = hist + 32768;
    unsigned long long* cand = (unsigned long long*)(csum + 1024);
    __shared__ int s_tb, s_cntgt, s_thr, s_cnt;
    const int b = blockIdx.x, tid = threadIdx.x;
    const float* sc = g_scores + (size_t)b * NTOT;

    for (int i = tid; i < 32768; i += 1024) hist[i] = 0;
    __syncthreads();
    for (int i = tid; i < NTOT; i += 1024)
        atomicAdd(&hist[__float_as_uint(sc[i]) >> 15], 1u);
    __syncthreads();
    { unsigned int cs = 0;
#pragma unroll 4
      for (int k = 0; k < 32; k++) cs += hist[tid*32 + k];
      csum[tid] = cs; }
    __syncthreads();
    if (tid == 0) {
        unsigned int accum = 0;
        int ch = 1023;
        for (; ch > 0; ch--) { if (accum + csum[ch] >= PRE) break; accum += csum[ch]; }
        int bk = ch*32 + 31;
        for (; bk > ch*32; bk--) { if (accum + hist[bk] >= PRE) break; accum += hist[bk]; }
        s_tb = bk; s_cntgt = (int)accum;
    }
    __syncthreads();
    const int tb = s_tb, cntgt = s_cntgt;

    for (int i = tid; i < 32768; i += 1024) hist[i] = 0;
    __syncthreads();
    for (int i = tid; i < NTOT; i += 1024) {
        unsigned int bits = __float_as_uint(sc[i]);
        if ((int)(bits >> 15) == tb) atomicAdd(&hist[bits & 0x7FFF], 1u);
    }
    __syncthreads();
    { unsigned int cs = 0;
#pragma unroll 4
      for (int k = 0; k < 32; k++) cs += hist[tid*32 + k];
      csum[tid] = cs; }
    __syncthreads();
    if (tid == 0) {
        unsigned int accum = (unsigned int)cntgt;
        int ch = 1023;
        for (; ch > 0; ch--) { if (accum + csum[ch] >= PRE) break; accum += csum[ch]; }
        int bk = ch*32 + 31;
        for (; bk > ch*32; bk--) { if (accum + hist[bk] >= PRE) break; accum += hist[bk]; }
        s_thr = (tb << 15) | bk;
        s_cnt = 0;
    }
    __syncthreads();
    const unsigned int thrbits = (unsigned int)s_thr;

    for (int i = tid; i < NTOT; i += 1024) {
        unsigned int bits = __float_as_uint(sc[i]);
        if (bits >= thrbits) {
            int pos = atomicAdd(&s_cnt, 1);
            if (pos < 1024)
                cand[pos] = ((unsigned long long)bits << 32) |
                            (unsigned long long)(0xFFFFFFFFu - (unsigned int)i);
        }
    }
    __syncthreads();
    int cnt = s_cnt; if (cnt > 1024) cnt = 1024;
    if (tid >= cnt) cand[tid] = 0ULL;
    __syncthreads();

    for (int k = 2; k <= 1024; k <<= 1) {
        for (int j = k >> 1; j > 0; j >>= 1) {
            int ixj = tid ^ j;
            if (ixj > tid) {
                unsigned long long a = cand[tid], c = cand[ixj];
                bool up = ((tid & k) == 0);
                if (up ? (a < c) : (a > c)) { cand[tid] = c; cand[ixj] = a; }
            }
            __syncthreads();
        }
    }
    if (tid < PRE) {
        unsigned long long key = cand[tid];
        unsigned int idx = 0xFFFFFFFFu - (unsigned int)(key & 0xFFFFFFFFull);
        g_topidx[b*PRE + tid]   = (int)idx;
        g_topscore[b*PRE + tid] = __uint_as_float((unsigned int)(key >> 32));
    }
}

#define W3S_FLOATS (36*513)
__global__ __launch_bounds__(512) void proposal_kernel(
    const float* __restrict__ w3, const float* __restrict__ b3,
    float* __restrict__ out)
{
    extern __shared__ float sm[];
    float*  w3s   = sm;
    float4* boxes = (float4*)(sm + W3S_FLOATS);
    float*  ss    = (float*)(boxes + PRE);
    int*    keep  = (int*)(ss + PRE);
    __shared__ int warpcnt[16];
    const int b = blockIdx.x;
    const int j = threadIdx.x;

    for (int i = j; i < 36*512; i += 512) {
        int row = i >> 9, c = i & 511;
        w3s[row*513 + c] = w3[i];
    }
    __syncthreads();

    const int   idx = g_topidx[b*PRE + j];
    const float s   = g_topscore[b*PRE + j];
    const int p = idx / 9, a = idx % 9;

    float so[4] = {0.f,0.f,0.f,0.f}, co[4] = {0.f,0.f,0.f,0.f};
    {
        const float* col = g_shared + (size_t)b * CIN * HW + p;
        const float* w0 = w3s + (a*4+0)*513;
        const float* w1r= w3s + (a*4+1)*513;
        const float* w2r= w3s + (a*4+2)*513;
        const float* w3r= w3s + (a*4+3)*513;
        for (int c = 0; c < CIN; c++) {
            float v = col[(size_t)c * HW];
            KAHAN_ADD(so[0], co[0], __fmul_rn(v, w0[c]));
            KAHAN_ADD(so[1], co[1], __fmul_rn(v, w1r[c]));
            KAHAN_ADD(so[2], co[2], __fmul_rn(v, w2r[c]));
            KAHAN_ADD(so[3], co[3], __fmul_rn(v, w3r[c]));
        }
    }
    const float o0 = __fadd_rn(__fsub_rn(so[0], co[0]), b3[a*4+0]);
    const float o1 = __fadd_rn(__fsub_rn(so[1], co[1]), b3[a*4+1]);
    const float o2 = __fadd_rn(__fsub_rn(so[2], co[2]), b3[a*4+2]);
    const float o3 = __fadd_rn(__fsub_rn(so[3], co[3]), b3[a*4+3]);

    const int ay = p / FW, ax = p % FW;
    const double cxd = (ax + 0.5) * 16.0;
    const double cyd = (ay + 0.5) * 16.0;
    const int si = a / 3, ri = a % 3;
    const double sz = (si == 0) ? 32.0 : (si == 1) ? 64.0 : 128.0;
    const double rr = (ri == 0) ? 0.5 : (ri == 1) ? 1.0 : 2.0;
    const float hf = (float)(sz * sqrt(rr));
    const float wf = (float)(sz / sqrt(rr));
    const float ax1 = (float)(cxd - (double)wf * 0.5);
    const float ay1 = (float)(cyd - (double)hf * 0.5);
    const float ax2 = (float)(cxd + (double)wf * 0.5);
    const float ay2 = (float)(cyd + (double)hf * 0.5);

    const float aw = __fsub_rn(ax2, ax1), ah = __fsub_rn(ay2, ay1);
    const float acx = __fadd_rn(ax1, __fmul_rn(0.5f, aw));
    const float acy = __fadd_rn(ay1, __fmul_rn(0.5f, ah));
    const float pcx = __fadd_rn(acx, __fmul_rn(o0, aw));
    const float pcy = __fadd_rn(acy, __fmul_rn(o1, ah));
    const float pw  = __fmul_rn(aw, (float)exp((double)o2));
    const float ph  = __fmul_rn(ah, (float)exp((double)o3));
    float x1 = __fsub_rn(pcx, __fmul_rn(0.5f, pw));
    float y1 = __fsub_rn(pcy, __fmul_rn(0.5f, ph));
    float x2 = __fadd_rn(pcx, __fmul_rn(0.5f, pw));
    float y2 = __fadd_rn(pcy, __fmul_rn(0.5f, ph));
    x1 = fminf(fmaxf(x1, 0.f), IMGW);
    y1 = fminf(fmaxf(y1, 0.f), IMGH);
    x2 = fminf(fmaxf(x2, 0.f), IMGW);
    y2 = fminf(fmaxf(y2, 0.f), IMGH);

    const float wb = x2 - x1, hb = y2 - y1;
    const bool valid = (wb >= 0.001f) && (hb >= 0.001f) && (s >= 0.5f);

    boxes[j] = make_float4(x1, y1, x2, y2);
    ss[j]    = s;
    keep[j]  = valid ? 1 : 0;
    __syncthreads();

    const float4 mb = boxes[j];
    const float myarea = (mb.z - mb.x) * (mb.w - mb.y);

    for (int i = 0; i < PRE - 1; i++) {
        __syncthreads();
        if (j > i && keep[i]) {
            float4 bi = boxes[i];
            float ltx = fmaxf(bi.x, mb.x), lty = fmaxf(bi.y, mb.y);
            float rbx = fminf(bi.z, mb.z), rby = fminf(bi.w, mb.w);
            float iw = fmaxf(rbx - ltx, 0.f), ih = fmaxf(rby - lty, 0.f);
            float inter = iw * ih;
            float ai = (bi.z - bi.x) * (bi.w - bi.y);
            float iou = inter / (ai + myarea - inter + 1e-9f);
            if (iou > 0.7f) keep[j] = 0;
        }
    }
    __syncthreads();

    const int lane = j & 31, warp = j >> 5;
    unsigned int m = __ballot_sync(0xffffffffu, keep[j] != 0);
    int pre = __popc(m & ((1u << lane) - 1u));
    if (lane == 0) warpcnt[warp] = __popc(m);
    __syncthreads();
    int base = 0, total = 0;
#pragma unroll
    for (int wi = 0; wi < 16; wi++) {
        int c = warpcnt[wi];
        if (wi < warp) base += c;
        total += c;
    }
    const int rank = base + pre;

    float* ob = out + (size_t)b * POST * 4;
    float* os = out + (size_t)BATCH * POST * 4 + (size_t)b * POST;

    if (j < POST && j >= total) {
        ob[j*4+0] = 0.f; ob[j*4+1] = 0.f; ob[j*4+2] = 0.f; ob[j*4+3] = 0.f;
        os[j] = 0.f;
    }
    if (keep[j] && rank < POST) {
        ob[rank*4+0] = mb.x; ob[rank*4+1] = mb.y;
        ob[rank*4+2] = mb.z; ob[rank*4+3] = mb.w;
        os[rank] = ss[j];
    }
}

extern "C" void kernel_launch(void* const* d_in, const int* in_sizes, int n_in,
                              void* d_out, int out_size)
{
    const float* fm = (const float*)d_in[0];
    const float* w1 = (const float*)d_in[1];
    const float* b1 = (const float*)d_in[2];
    const float* w2 = (const float*)d_in[3];
    const float* b2 = (const float*)d_in[4];
    const float* w3 = (const float*)d_in[5];
    const float* b3 = (const float*)d_in[6];
    float* out = (float*)d_out;

    zero_xsT_kernel<<<4096, 256>>>();
    prep_x_kernel<<<dim3(79, 16, BATCH), 256>>>(fm);
    prep_w_kernel<<<864, 256>>>(w1);

    const int conv_smem = 6*TILE_B + 16;   // 110608 B
    cudaFuncSetAttribute(conv_mma_kernel,
                         cudaFuncAttributeMaxDynamicSharedMemorySize, conv_smem);
    conv_mma_kernel<<<dim3(NPXT, CIN/OCB, BATCH), 256, conv_smem>>>(b1);

    cls_kernel<<<dim3((HW + 255) / 256, BATCH), 256>>>(w2, b2);

    const int topk_smem = 32768*4 + 1024*4 + 1024*8;
    cudaFuncSetAttribute(topk_kernel,
                         cudaFuncAttributeMaxDynamicSharedMemorySize, topk_smem);
    topk_kernel<<<BATCH, 1024, topk_smem>>>();

    const int prop_smem = W3S_FLOATS*4 + PRE*16 + PRE*4 + PRE*4;
    cudaFuncSetAttribute(proposal_kernel,
                         cudaFuncAttributeMaxDynamicSharedMemorySize, prop_smem);
    proposal_kernel<<<BATCH, PRE, prop_smem>>>(w3, b3, out);
}

// round 13
// speedup vs baseline: 3.6954x; 1.2587x over previous
#include <cuda_runtime.h>
#include <cuda_bf16.h>
#include <math.h>
#include <stdint.h>

#define BATCH 16
#define CIN   512
#define FH    50
#define FW    50
#define HW    2500
#define NANCH 9
#define NTOT  (HW*NANCH)
#define PRE   512
#define POST  128
#define IMGW  800.0f
#define IMGH  800.0f
#define OCB   128
#define PXB   128
#define NPXT  20
#define XROWS 2688
#define XPAD  64
#define RS    72                 // padded row stride (bf16 elems)
#define TILE_B (128*RS*2)        // 18432 bytes per split tile
#define BUF_B (6*TILE_B)         // 110592 bytes per stage buffer

#define KAHAN_ADD(s, c, p) do {                        \
    float _y = __fsub_rn((p), (c));                    \
    float _t = __fadd_rn((s), _y);                     \
    (c) = __fsub_rn(__fsub_rn(_t, (s)), _y);           \
    (s) = _t;                                          \
} while (0)

__device__ float g_shared[(size_t)BATCH*CIN*HW];
__device__ float g_scores[(size_t)BATCH*NTOT];
__device__ int   g_topidx[BATCH*PRE];
__device__ float g_topscore[BATCH*PRE];
__device__ __align__(16) __nv_bfloat16 g_xsT[9][BATCH][XROWS][CIN];
__device__ __align__(16) __nv_bfloat16 g_wA[(size_t)864*8192];

__device__ __forceinline__ uint32_t smem_u32(const void* p) {
    uint32_t a;
    asm("{ .reg .u64 t; cvta.to.shared.u64 t, %1; cvt.u32.u64 %0, t; }"
        : "=r"(a) : "l"(p));
    return a;
}
__device__ __forceinline__ void split3(float v, __nv_bfloat16& s0,
                                       __nv_bfloat16& s1, __nv_bfloat16& s2) {
    s0 = __float2bfloat16_rn(v);
    float r1 = __fsub_rn(v, __bfloat162float(s0));
    s1 = __float2bfloat16_rn(r1);
    float r2 = __fsub_rn(r1, __bfloat162float(s1));
    s2 = __float2bfloat16_rn(r2);
}

// zero only the pad rows (prep_x rewrites all data rows every call)
__global__ __launch_bounds__(256) void zero_pads_kernel() {
    // pad rows: [0, XPAD) and [XPAD+HW, XROWS)  -> 64 + 124 = 188 rows
    const int nrows = XPAD + (XROWS - XPAD - HW);
    size_t total = (size_t)9 * BATCH * nrows * CIN / 8;  // uint4 = 8 bf16
    uint4 z = make_uint4(0,0,0,0);
    for (size_t i = blockIdx.x * 256ull + threadIdx.x; i < total;
         i += (size_t)gridDim.x * 256ull) {
        size_t e = i * 8;
        int ic  = e % CIN;
        size_t r = e / CIN;
        int row = r % nrows;
        size_t jb = r / nrows;
        int b = jb % BATCH;
        int j = jb / BATCH;
        int xrow = (row < XPAD) ? row : (row - XPAD + XPAD + HW);
        *(uint4*)&g_xsT[j][b][xrow][ic] = z;
    }
}

__global__ __launch_bounds__(256) void prep_x_kernel(const float* __restrict__ x) {
    __shared__ float Xt[32][34];
    const int p0x = blockIdx.x * 32;
    const int i0  = blockIdx.y * 32;
    const int b   = blockIdx.z;
    const int tid = threadIdx.x;
    for (int e = tid; e < 32*34; e += 256) {
        int ic = e / 34, c = e % 34;
        int p = p0x - 1 + c;
        Xt[ic][c] = (p >= 0 && p < HW)
            ? x[((size_t)b*CIN + i0 + ic)*HW + p] : 0.f;
    }
    __syncthreads();
    for (int e = tid; e < 32*32; e += 256) {
        int pl = e >> 5, ic = e & 31;
        int p = p0x + pl;
        if (p >= HW) continue;
        int xcol = p % FW;
#pragma unroll
        for (int dxi = 0; dxi < 3; dxi++) {
            int xc = xcol + dxi - 1;
            float v = (xc >= 0 && xc < FW) ? Xt[ic][pl + dxi] : 0.f;
            __nv_bfloat16 s0, s1, s2;
            split3(v, s0, s1, s2);
            g_xsT[0*3 + dxi][b][p + XPAD][i0 + ic] = s0;
            g_xsT[1*3 + dxi][b][p + XPAD][i0 + ic] = s1;
            g_xsT[2*3 + dxi][b][p + XPAD][i0 + ic] = s2;
        }
    }
}

__global__ __launch_bounds__(256) void prep_w_kernel(const float* __restrict__ w1) {
    const int id = blockIdx.x;
    const int ocblk = id & 3;
    const int icblk = (id >> 2) & 7;
    const int tmp = id >> 5;
    const int t = tmp % 9;
    const int j = tmp / 9;
    __nv_bfloat16* dst = g_wA + (size_t)id * 8192;
    for (int e = threadIdx.x; e < 8192; e += 256) {
        int r = e >> 6, c = e & 63;
        int oc = ocblk*128 + r;
        int ic = icblk*64 + c;
        float w = w1[(size_t)oc*(CIN*9) + ic*9 + t];
        __nv_bfloat16 s0, s1, s2;
        split3(w, s0, s1, s2);
        dst[r*64 + c] = (j == 0) ? s0 : (j == 1) ? s1 : s2;
    }
}

// ==== K1: conv3x3 via bf16-split mma.sync, cp.async double-buffered ======
__device__ __forceinline__ void stage_chunk_async(
    uint32_t buf, int ch, int ocblk, int b, int p0, int tid)
{
    const int t = ch / 8, icblk = ch % 8;
    const int dy = t / 3 - 1, dxi = t % 3;
    // A tiles: 3 x 1024 16B chunks
    for (int e = tid; e < 3072; e += 256) {
        int j = e >> 10, r = (e >> 3) & 127, c8 = e & 7;
        const __nv_bfloat16* src = g_wA +
            (size_t)(((j*9 + t)*8 + icblk)*4 + ocblk) * 8192 + r*64 + c8*8;
        uint32_t d = buf + (uint32_t)(j*TILE_B + r*(RS*2) + c8*16);
        asm volatile("cp.async.cg.shared.global [%0], [%1], 16;"
                     :: "r"(d), "l"(src));
    }
    // B tiles: 3 x 1024 16B chunks
    const int rowbase = p0 + dy*FW + XPAD;
    for (int e = tid; e < 3072; e += 256) {
        int j = e >> 10, r = (e >> 3) & 127, c8 = e & 7;
        const __nv_bfloat16* src =
            &g_xsT[j*3 + dxi][b][rowbase + r][icblk*64] + c8*8;
        uint32_t d = buf + (uint32_t)(3*TILE_B + j*TILE_B + r*(RS*2) + c8*16);
        asm volatile("cp.async.cg.shared.global [%0], [%1], 16;"
                     :: "r"(d), "l"(src));
    }
    asm volatile("cp.async.commit_group;");
}

__global__ __launch_bounds__(256, 1)
void conv_mma_kernel(const float* __restrict__ b1) {
    extern __shared__ unsigned char dsm[];
    const uint32_t sb0 = (smem_u32(dsm) + 15u) & ~15u;

    const int tid  = threadIdx.x;
    const int wid  = tid >> 5;
    const int lane = tid & 31;
    const int pxblk = blockIdx.x, ocblk = blockIdx.y, b = blockIdx.z;
    const int p0 = pxblk * PXB;
    const int warp_m0 = (wid & 1) * 64;
    const int warp_n0 = (wid >> 1) * 32;

    float accL[4][4][4], accS[4][4][4];
#pragma unroll
    for (int mt = 0; mt < 4; mt++)
#pragma unroll
        for (int nt = 0; nt < 4; nt++)
#pragma unroll
            for (int r = 0; r < 4; r++) { accL[mt][nt][r] = 0.f; accS[mt][nt][r] = 0.f; }

    stage_chunk_async(sb0, 0, ocblk, b, p0, tid);

    for (int ch = 0; ch < 72; ch++) {
        const uint32_t cur = sb0 + (uint32_t)((ch & 1) * BUF_B);
        const uint32_t nxt = sb0 + (uint32_t)(((ch + 1) & 1) * BUF_B);

        asm volatile("cp.async.wait_group 0;" ::: "memory");
        __syncthreads();

        if (ch + 1 < 72)
            stage_chunk_async(nxt, ch + 1, ocblk, b, p0, tid);

        const uint32_t sbA = cur;
        const uint32_t sbB = cur + 3*TILE_B;

#pragma unroll
        for (int ks = 0; ks < 4; ks++) {
            const int k0 = ks * 16;
            uint32_t bf[3][4][2];
#pragma unroll
            for (int s = 0; s < 3; s++)
#pragma unroll
                for (int nt = 0; nt < 4; nt++) {
                    int row = warp_n0 + nt*8 + (lane & 7);
                    int colb = (k0 + ((lane >> 3) & 1)*8) * 2;
                    uint32_t a = sbB + s*TILE_B + row*(RS*2) + colb;
                    asm volatile(
                        "ldmatrix.sync.aligned.m8n8.x2.shared.b16 {%0,%1}, [%2];"
                        : "=r"(bf[s][nt][0]), "=r"(bf[s][nt][1]) : "r"(a));
                }
#pragma unroll
            for (int j = 0; j < 3; j++) {
                uint32_t af[4][4];
#pragma unroll
                for (int mt = 0; mt < 4; mt++) {
                    int row = warp_m0 + mt*16 + (lane & 15);
                    int colb = (k0 + (lane >> 4)*8) * 2;
                    uint32_t a = sbA + j*TILE_B + row*(RS*2) + colb;
                    asm volatile(
                        "ldmatrix.sync.aligned.m8n8.x4.shared.b16 {%0,%1,%2,%3}, [%4];"
                        : "=r"(af[mt][0]), "=r"(af[mt][1]),
                          "=r"(af[mt][2]), "=r"(af[mt][3]) : "r"(a));
                }
                const int nk = (j == 0) ? 3 : (j == 1) ? 2 : 1;
#pragma unroll
                for (int k = 0; k < 3; k++) {
                    if (k >= nk) break;
#pragma unroll
                    for (int mt = 0; mt < 4; mt++)
#pragma unroll
                        for (int nt = 0; nt < 4; nt++) {
                            asm volatile(
                                "mma.sync.aligned.m16n8k16.row.col.f32.bf16.bf16.f32 "
                                "{%0,%1,%2,%3}, {%4,%5,%6,%7}, {%8,%9}, {%0,%1,%2,%3};"
                                : "+f"(accS[mt][nt][0]), "+f"(accS[mt][nt][1]),
                                  "+f"(accS[mt][nt][2]), "+f"(accS[mt][nt][3])
                                : "r"(af[mt][0]), "r"(af[mt][1]),
                                  "r"(af[mt][2]), "r"(af[mt][3]),
                                  "r"(bf[k][nt][0]), "r"(bf[k][nt][1]));
                        }
                }
            }
        }
        if ((ch & 3) == 3) {
#pragma unroll
            for (int mt = 0; mt < 4; mt++)
#pragma unroll
                for (int nt = 0; nt < 4; nt++)
#pragma unroll
                    for (int r = 0; r < 4; r++) {
                        accL[mt][nt][r] = __fadd_rn(accL[mt][nt][r],
                                                    accS[mt][nt][r]);
                        accS[mt][nt][r] = 0.f;
                    }
        }
        __syncthreads();
    }

#pragma unroll
    for (int mt = 0; mt < 4; mt++) {
#pragma unroll
        for (int half = 0; half < 2; half++) {
            int oc = ocblk*128 + warp_m0 + mt*16 + (lane >> 2) + half*8;
            float bias = b1[oc];
            float* op = g_shared + ((size_t)b*CIN + oc)*HW;
#pragma unroll
            for (int nt = 0; nt < 4; nt++) {
#pragma unroll
                for (int e = 0; e < 2; e++) {
                    int px = p0 + warp_n0 + nt*8 + (lane & 3)*2 + e;
                    if (px < HW) {
                        float v = __fadd_rn(accL[mt][nt][half*2 + e], bias);
                        op[px] = fmaxf(v, 0.f);
                    }
                }
            }
        }
    }
}

__global__ __launch_bounds__(256) void cls_kernel(
    const float* __restrict__ w2, const float* __restrict__ b2)
{
    __shared__ float w2s[9][512];
    const int b = blockIdx.y;
    const int p = blockIdx.x * 256 + threadIdx.x;
    for (int i = threadIdx.x; i < 9*512; i += 256)
        w2s[i/512][i%512] = w2[i];
    __syncthreads();
    if (p >= HW) return;
    float acc[9], cmp[9];
#pragma unroll
    for (int a = 0; a < 9; a++) { acc[a] = 0.f; cmp[a] = 0.f; }
    const float* sp = g_shared + (size_t)b * CIN * HW + p;
    for (int c = 0; c < CIN; c++) {
        float v = sp[(size_t)c * HW];
#pragma unroll
        for (int a = 0; a < 9; a++)
            KAHAN_ADD(acc[a], cmp[a], __fmul_rn(v, w2s[a][c]));
    }
    float* outp = g_scores + (size_t)b * NTOT + (size_t)p * 9;
#pragma unroll
    for (int a = 0; a < 9; a++) {
        float logit = __fadd_rn(__fsub_rn(acc[a], cmp[a]), b2[a]);
        double sg = 1.0 / (1.0 + exp(-(double)logit));
        outp[a] = (float)sg;
    }
}

__global__ __launch_bounds__(1024) void topk_kernel()
{
    extern __shared__ unsigned char smraw[];
    unsigned int* hist = (unsigned int*)smraw;
    unsigned int* csum = hist + 32768;
    unsigned long long* cand = (unsigned long long*)(csum + 1024);
    __shared__ int s_tb, s_cntgt, s_thr, s_cnt;
    const int b = blockIdx.x, tid = threadIdx.x;
    const float* sc = g_scores + (size_t)b * NTOT;

    for (int i = tid; i < 32768; i += 1024) hist[i] = 0;
    __syncthreads();
    for (int i = tid; i < NTOT; i += 1024)
        atomicAdd(&hist[__float_as_uint(sc[i]) >> 15], 1u);
    __syncthreads();
    { unsigned int cs = 0;
#pragma unroll 4
      for (int k = 0; k < 32; k++) cs += hist[tid*32 + k];
      csum[tid] = cs; }
    __syncthreads();
    if (tid == 0) {
        unsigned int accum = 0;
        int ch = 1023;
        for (; ch > 0; ch--) { if (accum + csum[ch] >= PRE) break; accum += csum[ch]; }
        int bk = ch*32 + 31;
        for (; bk > ch*32; bk--) { if (accum + hist[bk] >= PRE) break; accum += hist[bk]; }
        s_tb = bk; s_cntgt = (int)accum;
    }
    __syncthreads();
    const int tb = s_tb, cntgt = s_cntgt;

    for (int i = tid; i < 32768; i += 1024) hist[i] = 0;
    __syncthreads();
    for (int i = tid; i < NTOT; i += 1024) {
        unsigned int bits = __float_as_uint(sc[i]);
        if ((int)(bits >> 15) == tb) atomicAdd(&hist[bits & 0x7FFF], 1u);
    }
    __syncthreads();
    { unsigned int cs = 0;
#pragma unroll 4
      for (int k = 0; k < 32; k++) cs += hist[tid*32 + k];
      csum[tid] = cs; }
    __syncthreads();
    if (tid == 0) {
        unsigned int accum = (unsigned int)cntgt;
        int ch = 1023;
        for (; ch > 0; ch--) { if (accum + csum[ch] >= PRE) break; accum += csum[ch]; }
        int bk = ch*32 + 31;
        for (; bk > ch*32; bk--) { if (accum + hist[bk] >= PRE) break; accum += hist[bk]; }
        s_thr = (tb << 15) | bk;
        s_cnt = 0;
    }
    __syncthreads();
    const unsigned int thrbits = (unsigned int)s_thr;

    for (int i = tid; i < NTOT; i += 1024) {
        unsigned int bits = __float_as_uint(sc[i]);
        if (bits >= thrbits) {
            int pos = atomicAdd(&s_cnt, 1);
            if (pos < 1024)
                cand[pos] = ((unsigned long long)bits << 32) |
                            (unsigned long long)(0xFFFFFFFFu - (unsigned int)i);
        }
    }
    __syncthreads();
    int cnt = s_cnt; if (cnt > 1024) cnt = 1024;
    if (tid >= cnt) cand[tid] = 0ULL;
    __syncthreads();

    for (int k = 2; k <= 1024; k <<= 1) {
        for (int j = k >> 1; j > 0; j >>= 1) {
            int ixj = tid ^ j;
            if (ixj > tid) {
                unsigned long long a = cand[tid], c = cand[ixj];
                bool up = ((tid & k) == 0);
                if (up ? (a < c) : (a > c)) { cand[tid] = c; cand[ixj] = a; }
            }
            __syncthreads();
        }
    }
    if (tid < PRE) {
        unsigned long long key = cand[tid];
        unsigned int idx = 0xFFFFFFFFu - (unsigned int)(key & 0xFFFFFFFFull);
        g_topidx[b*PRE + tid]   = (int)idx;
        g_topscore[b*PRE + tid] = __uint_as_float((unsigned int)(key >> 32));
    }
}

#define W3S_FLOATS (36*513)
__global__ __launch_bounds__(512) void proposal_kernel(
    const float* __restrict__ w3, const float* __restrict__ b3,
    float* __restrict__ out)
{
    extern __shared__ float sm[];
    float*  w3s   = sm;
    float4* boxes = (float4*)(sm + W3S_FLOATS);
    float*  ss    = (float*)(boxes + PRE);
    int*    keep  = (int*)(ss + PRE);
    __shared__ int warpcnt[16];
    const int b = blockIdx.x;
    const int j = threadIdx.x;

    for (int i = j; i < 36*512; i += 512) {
        int row = i >> 9, c = i & 511;
        w3s[row*513 + c] = w3[i];
    }
    __syncthreads();

    const int   idx = g_topidx[b*PRE + j];
    const float s   = g_topscore[b*PRE + j];
    const int p = idx / 9, a = idx % 9;

    float so[4] = {0.f,0.f,0.f,0.f}, co[4] = {0.f,0.f,0.f,0.f};
    {
        const float* col = g_shared + (size_t)b * CIN * HW + p;
        const float* w0 = w3s + (a*4+0)*513;
        const float* w1r= w3s + (a*4+1)*513;
        const float* w2r= w3s + (a*4+2)*513;
        const float* w3r= w3s + (a*4+3)*513;
        for (int c = 0; c < CIN; c++) {
            float v = col[(size_t)c * HW];
            KAHAN_ADD(so[0], co[0], __fmul_rn(v, w0[c]));
            KAHAN_ADD(so[1], co[1], __fmul_rn(v, w1r[c]));
            KAHAN_ADD(so[2], co[2], __fmul_rn(v, w2r[c]));
            KAHAN_ADD(so[3], co[3], __fmul_rn(v, w3r[c]));
        }
    }
    const float o0 = __fadd_rn(__fsub_rn(so[0], co[0]), b3[a*4+0]);
    const float o1 = __fadd_rn(__fsub_rn(so[1], co[1]), b3[a*4+1]);
    const float o2 = __fadd_rn(__fsub_rn(so[2], co[2]), b3[a*4+2]);
    const float o3 = __fadd_rn(__fsub_rn(so[3], co[3]), b3[a*4+3]);

    const int ay = p / FW, ax = p % FW;
    const double cxd = (ax + 0.5) * 16.0;
    const double cyd = (ay + 0.5) * 16.0;
    const int si = a / 3, ri = a % 3;
    const double sz = (si == 0) ? 32.0 : (si == 1) ? 64.0 : 128.0;
    const double rr = (ri == 0) ? 0.5 : (ri == 1) ? 1.0 : 2.0;
    const float hf = (float)(sz * sqrt(rr));
    const float wf = (float)(sz / sqrt(rr));
    const float ax1 = (float)(cxd - (double)wf * 0.5);
    const float ay1 = (float)(cyd - (double)hf * 0.5);
    const float ax2 = (float)(cxd + (double)wf * 0.5);
    const float ay2 = (float)(cyd + (double)hf * 0.5);

    const float aw = __fsub_rn(ax2, ax1), ah = __fsub_rn(ay2, ay1);
    const float acx = __fadd_rn(ax1, __fmul_rn(0.5f, aw));
    const float acy = __fadd_rn(ay1, __fmul_rn(0.5f, ah));
    const float pcx = __fadd_rn(acx, __fmul_rn(o0, aw));
    const float pcy = __fadd_rn(acy, __fmul_rn(o1, ah));
    const float pw  = __fmul_rn(aw, (float)exp((double)o2));
    const float ph  = __fmul_rn(ah, (float)exp((double)o3));
    float x1 = __fsub_rn(pcx, __fmul_rn(0.5f, pw));
    float y1 = __fsub_rn(pcy, __fmul_rn(0.5f, ph));
    float x2 = __fadd_rn(pcx, __fmul_rn(0.5f, pw));
    float y2 = __fadd_rn(pcy, __fmul_rn(0.5f, ph));
    x1 = fminf(fmaxf(x1, 0.f), IMGW);
    y1 = fminf(fmaxf(y1, 0.f), IMGH);
    x2 = fminf(fmaxf(x2, 0.f), IMGW);
    y2 = fminf(fmaxf(y2, 0.f), IMGH);

    const float wb = x2 - x1, hb = y2 - y1;
    const bool valid = (wb >= 0.001f) && (hb >= 0.001f) && (s >= 0.5f);

    boxes[j] = make_float4(x1, y1, x2, y2);
    ss[j]    = s;
    keep[j]  = valid ? 1 : 0;
    __syncthreads();

    const float4 mb = boxes[j];
    const float myarea = (mb.z - mb.x) * (mb.w - mb.y);

    for (int i = 0; i < PRE - 1; i++) {
        __syncthreads();
        if (j > i && keep[i]) {
            float4 bi = boxes[i];
            float ltx = fmaxf(bi.x, mb.x), lty = fmaxf(bi.y, mb.y);
            float rbx = fminf(bi.z, mb.z), rby = fminf(bi.w, mb.w);
            float iw = fmaxf(rbx - ltx, 0.f), ih = fmaxf(rby - lty, 0.f);
            float inter = iw * ih;
            float ai = (bi.z - bi.x) * (bi.w - bi.y);
            float iou = inter / (ai + myarea - inter + 1e-9f);
            if (iou > 0.7f) keep[j] = 0;
        }
    }
    __syncthreads();

    const int lane = j & 31, warp = j >> 5;
    unsigned int m = __ballot_sync(0xffffffffu, keep[j] != 0);
    int pre = __popc(m & ((1u << lane) - 1u));
    if (lane == 0) warpcnt[warp] = __popc(m);
    __syncthreads();
    int base = 0, total = 0;
#pragma unroll
    for (int wi = 0; wi < 16; wi++) {
        int c = warpcnt[wi];
        if (wi < warp) base += c;
        total += c;
    }
    const int rank = base + pre;

    float* ob = out + (size_t)b * POST * 4;
    float* os = out + (size_t)BATCH * POST * 4 + (size_t)b * POST;

    if (j < POST && j >= total) {
        ob[j*4+0] = 0.f; ob[j*4+1] = 0.f; ob[j*4+2] = 0.f; ob[j*4+3] = 0.f;
        os[j] = 0.f;
    }
    if (keep[j] && rank < POST) {
        ob[rank*4+0] = mb.x; ob[rank*4+1] = mb.y;
        ob[rank*4+2] = mb.z; ob[rank*4+3] = mb.w;
        os[rank] = ss[j];
    }
}

extern "C" void kernel_launch(void* const* d_in, const int* in_sizes, int n_in,
                              void* d_out, int out_size)
{
    const float* fm = (const float*)d_in[0];
    const float* w1 = (const float*)d_in[1];
    const float* b1 = (const float*)d_in[2];
    const float* w2 = (const float*)d_in[3];
    const float* b2 = (const float*)d_in[4];
    const float* w3 = (const float*)d_in[5];
    const float* b3 = (const float*)d_in[6];
    float* out = (float*)d_out;

    zero_pads_kernel<<<1024, 256>>>();
    prep_x_kernel<<<dim3(79, 16, BATCH), 256>>>(fm);
    prep_w_kernel<<<864, 256>>>(w1);

    const int conv_smem = 2*BUF_B + 16;   // 221200 B
    cudaFuncSetAttribute(conv_mma_kernel,
                         cudaFuncAttributeMaxDynamicSharedMemorySize, conv_smem);
    conv_mma_kernel<<<dim3(NPXT, CIN/OCB, BATCH), 256, conv_smem>>>(b1);

    cls_kernel<<<dim3((HW + 255) / 256, BATCH), 256>>>(w2, b2);

    const int topk_smem = 32768*4 + 1024*4 + 1024*8;
    cudaFuncSetAttribute(topk_kernel,
                         cudaFuncAttributeMaxDynamicSharedMemorySize, topk_smem);
    topk_kernel<<<BATCH, 1024, topk_smem>>>();

    const int prop_smem = W3S_FLOATS*4 + PRE*16 + PRE*4 + PRE*4;
    cudaFuncSetAttribute(proposal_kernel,
                         cudaFuncAttributeMaxDynamicSharedMemorySize, prop_smem);
    proposal_kernel<<<BATCH, PRE, prop_smem>>>(w3, b3, out);
}

// round 14
// speedup vs baseline: 3.7317x; 1.0098x over previous
#include <cuda_runtime.h>
#include <cuda_bf16.h>
#include <math.h>
#include <stdint.h>

#define BATCH 16
#define CIN   512
#define FH    50
#define FW    50
#define HW    2500
#define NANCH 9
#define NTOT  (HW*NANCH)
#define PRE   512
#define POST  128
#define IMGW  800.0f
#define IMGH  800.0f
#define OCB   128
#define PXB   128
#define NPXT  20
#define XROWS 2688
#define XPAD  64
#define RS    72
#define TILE_B (128*RS*2)
#define BUF_B (6*TILE_B)

#define KAHAN_ADD(s, c, p) do {                        \
    float _y = __fsub_rn((p), (c));                    \
    float _t = __fadd_rn((s), _y);                     \
    (c) = __fsub_rn(__fsub_rn(_t, (s)), _y);           \
    (s) = _t;                                          \
} while (0)

__device__ float g_shared[(size_t)BATCH*CIN*HW];
__device__ float g_scores[(size_t)BATCH*NTOT];
__device__ int   g_topidx[BATCH*PRE];
__device__ float g_topscore[BATCH*PRE];
__device__ __align__(16) __nv_bfloat16 g_xsT[9][BATCH][XROWS][CIN];
__device__ __align__(16) __nv_bfloat16 g_wA[(size_t)864*8192];

__device__ __forceinline__ uint32_t smem_u32(const void* p) {
    uint32_t a;
    asm("{ .reg .u64 t; cvta.to.shared.u64 t, %1; cvt.u32.u64 %0, t; }"
        : "=r"(a) : "l"(p));
    return a;
}
__device__ __forceinline__ void split3(float v, __nv_bfloat16& s0,
                                       __nv_bfloat16& s1, __nv_bfloat16& s2) {
    s0 = __float2bfloat16_rn(v);
    float r1 = __fsub_rn(v, __bfloat162float(s0));
    s1 = __float2bfloat16_rn(r1);
    float r2 = __fsub_rn(r1, __bfloat162float(s1));
    s2 = __float2bfloat16_rn(r2);
}

__global__ __launch_bounds__(256) void zero_pads_kernel() {
    const int nrows = XPAD + (XROWS - XPAD - HW);
    size_t total = (size_t)9 * BATCH * nrows * CIN / 8;
    uint4 z = make_uint4(0,0,0,0);
    for (size_t i = blockIdx.x * 256ull + threadIdx.x; i < total;
         i += (size_t)gridDim.x * 256ull) {
        size_t e = i * 8;
        int ic  = e % CIN;
        size_t r = e / CIN;
        int row = r % nrows;
        size_t jb = r / nrows;
        int b = jb % BATCH;
        int j = jb / BATCH;
        int xrow = (row < XPAD) ? row : (row - XPAD + XPAD + HW);
        *(uint4*)&g_xsT[j][b][xrow][ic] = z;
    }
}

__global__ __launch_bounds__(256) void prep_x_kernel(const float* __restrict__ x) {
    __shared__ float Xt[32][34];
    const int p0x = blockIdx.x * 32;
    const int i0  = blockIdx.y * 32;
    const int b   = blockIdx.z;
    const int tid = threadIdx.x;
    for (int e = tid; e < 32*34; e += 256) {
        int ic = e / 34, c = e % 34;
        int p = p0x - 1 + c;
        Xt[ic][c] = (p >= 0 && p < HW)
            ? x[((size_t)b*CIN + i0 + ic)*HW + p] : 0.f;
    }
    __syncthreads();
    for (int e = tid; e < 32*32; e += 256) {
        int pl = e >> 5, ic = e & 31;
        int p = p0x + pl;
        if (p >= HW) continue;
        int xcol = p % FW;
#pragma unroll
        for (int dxi = 0; dxi < 3; dxi++) {
            int xc = xcol + dxi - 1;
            float v = (xc >= 0 && xc < FW) ? Xt[ic][pl + dxi] : 0.f;
            __nv_bfloat16 s0, s1, s2;
            split3(v, s0, s1, s2);
            g_xsT[0*3 + dxi][b][p + XPAD][i0 + ic] = s0;
            g_xsT[1*3 + dxi][b][p + XPAD][i0 + ic] = s1;
            g_xsT[2*3 + dxi][b][p + XPAD][i0 + ic] = s2;
        }
    }
}

__global__ __launch_bounds__(256) void prep_w_kernel(const float* __restrict__ w1) {
    const int id = blockIdx.x;
    const int ocblk = id & 3;
    const int icblk = (id >> 2) & 7;
    const int tmp = id >> 5;
    const int t = tmp % 9;
    const int j = tmp / 9;
    __nv_bfloat16* dst = g_wA + (size_t)id * 8192;
    for (int e = threadIdx.x; e < 8192; e += 256) {
        int r = e >> 6, c = e & 63;
        int oc = ocblk*128 + r;
        int ic = icblk*64 + c;
        float w = w1[(size_t)oc*(CIN*9) + ic*9 + t];
        __nv_bfloat16 s0, s1, s2;
        split3(w, s0, s1, s2);
        dst[r*64 + c] = (j == 0) ? s0 : (j == 1) ? s1 : s2;
    }
}

__device__ __forceinline__ void stage_chunk_async(
    uint32_t buf, int ch, int ocblk, int b, int p0, int tid)
{
    const int t = ch / 8, icblk = ch % 8;
    const int dy = t / 3 - 1, dxi = t % 3;
    for (int e = tid; e < 3072; e += 256) {
        int j = e >> 10, r = (e >> 3) & 127, c8 = e & 7;
        const __nv_bfloat16* src = g_wA +
            (size_t)(((j*9 + t)*8 + icblk)*4 + ocblk) * 8192 + r*64 + c8*8;
        uint32_t d = buf + (uint32_t)(j*TILE_B + r*(RS*2) + c8*16);
        asm volatile("cp.async.cg.shared.global [%0], [%1], 16;"
                     :: "r"(d), "l"(src));
    }
    const int rowbase = p0 + dy*FW + XPAD;
    for (int e = tid; e < 3072; e += 256) {
        int j = e >> 10, r = (e >> 3) & 127, c8 = e & 7;
        const __nv_bfloat16* src =
            &g_xsT[j*3 + dxi][b][rowbase + r][icblk*64] + c8*8;
        uint32_t d = buf + (uint32_t)(3*TILE_B + j*TILE_B + r*(RS*2) + c8*16);
        asm volatile("cp.async.cg.shared.global [%0], [%1], 16;"
                     :: "r"(d), "l"(src));
    }
    asm volatile("cp.async.commit_group;");
}

__global__ __launch_bounds__(256, 1)
void conv_mma_kernel(const float* __restrict__ b1) {
    extern __shared__ unsigned char dsm[];
    const uint32_t sb0 = (smem_u32(dsm) + 15u) & ~15u;

    const int tid  = threadIdx.x;
    const int wid  = tid >> 5;
    const int lane = tid & 31;
    const int pxblk = blockIdx.x, ocblk = blockIdx.y, b = blockIdx.z;
    const int p0 = pxblk * PXB;
    const int warp_m0 = (wid & 1) * 64;
    const int warp_n0 = (wid >> 1) * 32;

    float accL[4][4][4], accS[4][4][4];
#pragma unroll
    for (int mt = 0; mt < 4; mt++)
#pragma unroll
        for (int nt = 0; nt < 4; nt++)
#pragma unroll
            for (int r = 0; r < 4; r++) { accL[mt][nt][r] = 0.f; accS[mt][nt][r] = 0.f; }

    stage_chunk_async(sb0, 0, ocblk, b, p0, tid);

    for (int ch = 0; ch < 72; ch++) {
        const uint32_t cur = sb0 + (uint32_t)((ch & 1) * BUF_B);
        const uint32_t nxt = sb0 + (uint32_t)(((ch + 1) & 1) * BUF_B);

        asm volatile("cp.async.wait_group 0;" ::: "memory");
        __syncthreads();   // all warps done with prior compute of `nxt` buffer

        if (ch + 1 < 72)
            stage_chunk_async(nxt, ch + 1, ocblk, b, p0, tid);

        const uint32_t sbA = cur;
        const uint32_t sbB = cur + 3*TILE_B;

#pragma unroll
        for (int ks = 0; ks < 4; ks++) {
            const int k0 = ks * 16;
            uint32_t bf[3][4][2];
#pragma unroll
            for (int s = 0; s < 3; s++)
#pragma unroll
                for (int nt = 0; nt < 4; nt++) {
                    int row = warp_n0 + nt*8 + (lane & 7);
                    int colb = (k0 + ((lane >> 3) & 1)*8) * 2;
                    uint32_t a = sbB + s*TILE_B + row*(RS*2) + colb;
                    asm volatile(
                        "ldmatrix.sync.aligned.m8n8.x2.shared.b16 {%0,%1}, [%2];"
                        : "=r"(bf[s][nt][0]), "=r"(bf[s][nt][1]) : "r"(a));
                }
#pragma unroll
            for (int j = 0; j < 3; j++) {
                uint32_t af[4][4];
#pragma unroll
                for (int mt = 0; mt < 4; mt++) {
                    int row = warp_m0 + mt*16 + (lane & 15);
                    int colb = (k0 + (lane >> 4)*8) * 2;
                    uint32_t a = sbA + j*TILE_B + row*(RS*2) + colb;
                    asm volatile(
                        "ldmatrix.sync.aligned.m8n8.x4.shared.b16 {%0,%1,%2,%3}, [%4];"
                        : "=r"(af[mt][0]), "=r"(af[mt][1]),
                          "=r"(af[mt][2]), "=r"(af[mt][3]) : "r"(a));
                }
                const int nk = (j == 0) ? 3 : (j == 1) ? 2 : 1;
#pragma unroll
                for (int k = 0; k < 3; k++) {
                    if (k >= nk) break;
#pragma unroll
                    for (int mt = 0; mt < 4; mt++)
#pragma unroll
                        for (int nt = 0; nt < 4; nt++) {
                            asm volatile(
                                "mma.sync.aligned.m16n8k16.row.col.f32.bf16.bf16.f32 "
                                "{%0,%1,%2,%3}, {%4,%5,%6,%7}, {%8,%9}, {%0,%1,%2,%3};"
                                : "+f"(accS[mt][nt][0]), "+f"(accS[mt][nt][1]),
                                  "+f"(accS[mt][nt][2]), "+f"(accS[mt][nt][3])
                                : "r"(af[mt][0]), "r"(af[mt][1]),
                                  "r"(af[mt][2]), "r"(af[mt][3]),
                                  "r"(bf[k][nt][0]), "r"(bf[k][nt][1]));
                        }
                }
            }
        }
        if ((ch & 3) == 3) {
#pragma unroll
            for (int mt = 0; mt < 4; mt++)
#pragma unroll
                for (int nt = 0; nt < 4; nt++)
#pragma unroll
                    for (int r = 0; r < 4; r++) {
                        accL[mt][nt][r] = __fadd_rn(accL[mt][nt][r],
                                                    accS[mt][nt][r]);
                        accS[mt][nt][r] = 0.f;
                    }
        }
        // no bottom sync: top sync of next iteration provides the barrier
    }

#pragma unroll
    for (int mt = 0; mt < 4; mt++) {
#pragma unroll
        for (int half = 0; half < 2; half++) {
            int oc = ocblk*128 + warp_m0 + mt*16 + (lane >> 2) + half*8;
            float bias = b1[oc];
            float* op = g_shared + ((size_t)b*CIN + oc)*HW;
#pragma unroll
            for (int nt = 0; nt < 4; nt++) {
#pragma unroll
                for (int e = 0; e < 2; e++) {
                    int px = p0 + warp_n0 + nt*8 + (lane & 3)*2 + e;
                    if (px < HW) {
                        float v = __fadd_rn(accL[mt][nt][half*2 + e], bias);
                        op[px] = fmaxf(v, 0.f);
                    }
                }
            }
        }
    }
}

__global__ __launch_bounds__(256) void cls_kernel(
    const float* __restrict__ w2, const float* __restrict__ b2)
{
    __shared__ float w2s[9][512];
    const int b = blockIdx.y;
    const int p = blockIdx.x * 256 + threadIdx.x;
    for (int i = threadIdx.x; i < 9*512; i += 256)
        w2s[i/512][i%512] = w2[i];
    __syncthreads();
    if (p >= HW) return;
    float acc[9], cmp[9];
#pragma unroll
    for (int a = 0; a < 9; a++) { acc[a] = 0.f; cmp[a] = 0.f; }
    const float* sp = g_shared + (size_t)b * CIN * HW + p;
    for (int c = 0; c < CIN; c++) {
        float v = sp[(size_t)c * HW];
#pragma unroll
        for (int a = 0; a < 9; a++)
            KAHAN_ADD(acc[a], cmp[a], __fmul_rn(v, w2s[a][c]));
    }
    float* outp = g_scores + (size_t)b * NTOT + (size_t)p * 9;
#pragma unroll
    for (int a = 0; a < 9; a++) {
        float logit = __fadd_rn(__fsub_rn(acc[a], cmp[a]), b2[a]);
        double sg = 1.0 / (1.0 + exp(-(double)logit));
        outp[a] = (float)sg;
    }
}

__global__ __launch_bounds__(1024) void topk_kernel()
{
    extern __shared__ unsigned char smraw[];
    unsigned int* hist = (unsigned int*)smraw;
    unsigned int* csum = hist + 32768;
    unsigned long long* cand = (unsigned long long*)(csum + 1024);
    __shared__ int s_tb, s_cntgt, s_thr, s_cnt;
    const int b = blockIdx.x, tid = threadIdx.x;
    const float* sc = g_scores + (size_t)b * NTOT;

    for (int i = tid; i < 32768; i += 1024) hist[i] = 0;
    __syncthreads();
    for (int i = tid; i < NTOT; i += 1024)
        atomicAdd(&hist[__float_as_uint(sc[i]) >> 15], 1u);
    __syncthreads();
    { unsigned int cs = 0;
#pragma unroll 4
      for (int k = 0; k < 32; k++) cs += hist[tid*32 + k];
      csum[tid] = cs; }
    __syncthreads();
    if (tid == 0) {
        unsigned int accum = 0;
        int ch = 1023;
        for (; ch > 0; ch--) { if (accum + csum[ch] >= PRE) break; accum += csum[ch]; }
        int bk = ch*32 + 31;
        for (; bk > ch*32; bk--) { if (accum + hist[bk] >= PRE) break; accum += hist[bk]; }
        s_tb = bk; s_cntgt = (int)accum;
    }
    __syncthreads();
    const int tb = s_tb, cntgt = s_cntgt;

    for (int i = tid; i < 32768; i += 1024) hist[i] = 0;
    __syncthreads();
    for (int i = tid; i < NTOT; i += 1024) {
        unsigned int bits = __float_as_uint(sc[i]);
        if ((int)(bits >> 15) == tb) atomicAdd(&hist[bits & 0x7FFF], 1u);
    }
    __syncthreads();
    { unsigned int cs = 0;
#pragma unroll 4
      for (int k = 0; k < 32; k++) cs += hist[tid*32 + k];
      csum[tid] = cs; }
    __syncthreads();
    if (tid == 0) {
        unsigned int accum = (unsigned int)cntgt;
        int ch = 1023;
        for (; ch > 0; ch--) { if (accum + csum[ch] >= PRE) break; accum += csum[ch]; }
        int bk = ch*32 + 31;
        for (; bk > ch*32; bk--) { if (accum + hist[bk] >= PRE) break; accum += hist[bk]; }
        s_thr = (tb << 15) | bk;
        s_cnt = 0;
    }
    __syncthreads();
    const unsigned int thrbits = (unsigned int)s_thr;

    for (int i = tid; i < NTOT; i += 1024) {
        unsigned int bits = __float_as_uint(sc[i]);
        if (bits >= thrbits) {
            int pos = atomicAdd(&s_cnt, 1);
            if (pos < 1024)
                cand[pos] = ((unsigned long long)bits << 32) |
                            (unsigned long long)(0xFFFFFFFFu - (unsigned int)i);
        }
    }
    __syncthreads();
    int cnt = s_cnt; if (cnt > 1024) cnt = 1024;
    if (tid >= cnt) cand[tid] = 0ULL;
    __syncthreads();

    for (int k = 2; k <= 1024; k <<= 1) {
        for (int j = k >> 1; j > 0; j >>= 1) {
            int ixj = tid ^ j;
            if (ixj > tid) {
                unsigned long long a = cand[tid], c = cand[ixj];
                bool up = ((tid & k) == 0);
                if (up ? (a < c) : (a > c)) { cand[tid] = c; cand[ixj] = a; }
            }
            __syncthreads();
        }
    }
    if (tid < PRE) {
        unsigned long long key = cand[tid];
        unsigned int idx = 0xFFFFFFFFu - (unsigned int)(key & 0xFFFFFFFFull);
        g_topidx[b*PRE + tid]   = (int)idx;
        g_topscore[b*PRE + tid] = __uint_as_float((unsigned int)(key >> 32));
    }
}

#define W3S_FLOATS (36*513)
__global__ __launch_bounds__(512) void proposal_kernel(
    const float* __restrict__ w3, const float* __restrict__ b3,
    float* __restrict__ out)
{
    extern __shared__ float sm[];
    float*  w3s   = sm;
    float4* boxes = (float4*)(sm + W3S_FLOATS);
    float*  ss    = (float*)(boxes + PRE);
    int*    keep  = (int*)(ss + PRE);
    __shared__ uint32_t aliveW[16];
    __shared__ int warpcnt[16];
    const int b = blockIdx.x;
    const int j = threadIdx.x;
    const int lane = j & 31, warp = j >> 5;

    for (int i = j; i < 36*512; i += 512) {
        int row = i >> 9, c = i & 511;
        w3s[row*513 + c] = w3[i];
    }
    __syncthreads();

    const int   idx = g_topidx[b*PRE + j];
    const float s   = g_topscore[b*PRE + j];
    const int p = idx / 9, a = idx % 9;

    float so[4] = {0.f,0.f,0.f,0.f}, co[4] = {0.f,0.f,0.f,0.f};
    {
        const float* col = g_shared + (size_t)b * CIN * HW + p;
        const float* w0 = w3s + (a*4+0)*513;
        const float* w1r= w3s + (a*4+1)*513;
        const float* w2r= w3s + (a*4+2)*513;
        const float* w3r= w3s + (a*4+3)*513;
        for (int c = 0; c < CIN; c++) {
            float v = col[(size_t)c * HW];
            KAHAN_ADD(so[0], co[0], __fmul_rn(v, w0[c]));
            KAHAN_ADD(so[1], co[1], __fmul_rn(v, w1r[c]));
            KAHAN_ADD(so[2], co[2], __fmul_rn(v, w2r[c]));
            KAHAN_ADD(so[3], co[3], __fmul_rn(v, w3r[c]));
        }
    }
    const float o0 = __fadd_rn(__fsub_rn(so[0], co[0]), b3[a*4+0]);
    const float o1 = __fadd_rn(__fsub_rn(so[1], co[1]), b3[a*4+1]);
    const float o2 = __fadd_rn(__fsub_rn(so[2], co[2]), b3[a*4+2]);
    const float o3 = __fadd_rn(__fsub_rn(so[3], co[3]), b3[a*4+3]);

    const int ay = p / FW, ax = p % FW;
    const double cxd = (ax + 0.5) * 16.0;
    const double cyd = (ay + 0.5) * 16.0;
    const int si = a / 3, ri = a % 3;
    const double sz = (si == 0) ? 32.0 : (si == 1) ? 64.0 : 128.0;
    const double rr = (ri == 0) ? 0.5 : (ri == 1) ? 1.0 : 2.0;
    const float hf = (float)(sz * sqrt(rr));
    const float wf = (float)(sz / sqrt(rr));
    const float ax1 = (float)(cxd - (double)wf * 0.5);
    const float ay1 = (float)(cyd - (double)hf * 0.5);
    const float ax2 = (float)(cxd + (double)wf * 0.5);
    const float ay2 = (float)(cyd + (double)hf * 0.5);

    const float aw = __fsub_rn(ax2, ax1), ah = __fsub_rn(ay2, ay1);
    const float acx = __fadd_rn(ax1, __fmul_rn(0.5f, aw));
    const float acy = __fadd_rn(ay1, __fmul_rn(0.5f, ah));
    const float pcx = __fadd_rn(acx, __fmul_rn(o0, aw));
    const float pcy = __fadd_rn(acy, __fmul_rn(o1, ah));
    const float pw  = __fmul_rn(aw, (float)exp((double)o2));
    const float ph  = __fmul_rn(ah, (float)exp((double)o3));
    float x1 = __fsub_rn(pcx, __fmul_rn(0.5f, pw));
    float y1 = __fsub_rn(pcy, __fmul_rn(0.5f, ph));
    float x2 = __fadd_rn(pcx, __fmul_rn(0.5f, pw));
    float y2 = __fadd_rn(pcy, __fmul_rn(0.5f, ph));
    x1 = fminf(fmaxf(x1, 0.f), IMGW);
    y1 = fminf(fmaxf(y1, 0.f), IMGH);
    x2 = fminf(fmaxf(x2, 0.f), IMGW);
    y2 = fminf(fmaxf(y2, 0.f), IMGH);

    const float wb = x2 - x1, hb = y2 - y1;
    const bool valid = (wb >= 0.001f) && (hb >= 0.001f) && (s >= 0.5f);

    boxes[j] = make_float4(x1, y1, x2, y2);
    ss[j]    = s;
    __syncthreads();

    const float4 mb = boxes[j];
    const float myarea = (mb.z - mb.x) * (mb.w - mb.y);

    // ---- precompute per-thread suppression mask over all i<j ----
    uint32_t msk[16];
#pragma unroll
    for (int c = 0; c < 16; c++) {
        uint32_t w = 0;
        for (int bit = 0; bit < 32; bit++) {
            int i = c*32 + bit;
            if (i < j) {
                float4 bi = boxes[i];
                float ltx = fmaxf(bi.x, mb.x), lty = fmaxf(bi.y, mb.y);
                float rbx = fminf(bi.z, mb.z), rby = fminf(bi.w, mb.w);
                float iw = fmaxf(rbx - ltx, 0.f), ih = fmaxf(rby - lty, 0.f);
                float inter = iw * ih;
                float ai = (bi.z - bi.x) * (bi.w - bi.y);
                float iou = inter / (ai + myarea - inter + 1e-9f);
                if (iou > 0.7f) w |= (1u << bit);
            }
        }
        msk[c] = w;
    }

    // ---- chunked greedy NMS: 16 block syncs instead of 511 ----
    int mykeep = valid ? 1 : 0;
    for (int c = 0; c < 16; c++) {
        if (warp == c) {
            unsigned alive = __ballot_sync(0xffffffffu, mykeep);
            for (int bbit = 0; bbit < 32; bbit++) {
                unsigned sup = __ballot_sync(0xffffffffu,
                                             (msk[c] >> bbit) & 1u);
                if ((alive >> bbit) & 1u) alive &= ~sup;
            }
            mykeep = (alive >> lane) & 1u;
            if (lane == 0) aliveW[c] = alive;
        }
        __syncthreads();
        if (warp > c) {
            if (msk[c] & aliveW[c]) mykeep = 0;
        }
    }
    keep[j] = mykeep;
    __syncthreads();

    unsigned int m = __ballot_sync(0xffffffffu, keep[j] != 0);
    int pre = __popc(m & ((1u << lane) - 1u));
    if (lane == 0) warpcnt[warp] = __popc(m);
    __syncthreads();
    int base = 0, total = 0;
#pragma unroll
    for (int wi = 0; wi < 16; wi++) {
        int c = warpcnt[wi];
        if (wi < warp) base += c;
        total += c;
    }
    const int rank = base + pre;

    float* ob = out + (size_t)b * POST * 4;
    float* os = out + (size_t)BATCH * POST * 4 + (size_t)b * POST;

    if (j < POST && j >= total) {
        ob[j*4+0] = 0.f; ob[j*4+1] = 0.f; ob[j*4+2] = 0.f; ob[j*4+3] = 0.f;
        os[j] = 0.f;
    }
    if (keep[j] && rank < POST) {
        ob[rank*4+0] = mb.x; ob[rank*4+1] = mb.y;
        ob[rank*4+2] = mb.z; ob[rank*4+3] = mb.w;
        os[rank] = ss[j];
    }
}

extern "C" void kernel_launch(void* const* d_in, const int* in_sizes, int n_in,
                              void* d_out, int out_size)
{
    const float* fm = (const float*)d_in[0];
    const float* w1 = (const float*)d_in[1];
    const float* b1 = (const float*)d_in[2];
    const float* w2 = (const float*)d_in[3];
    const float* b2 = (const float*)d_in[4];
    const float* w3 = (const float*)d_in[5];
    const float* b3 = (const float*)d_in[6];
    float* out = (float*)d_out;

    zero_pads_kernel<<<1024, 256>>>();
    prep_x_kernel<<<dim3(79, 16, BATCH), 256>>>(fm);
    prep_w_kernel<<<864, 256>>>(w1);

    const int conv_smem = 2*BUF_B + 16;
    cudaFuncSetAttribute(conv_mma_kernel,
                         cudaFuncAttributeMaxDynamicSharedMemorySize, conv_smem);
    conv_mma_kernel<<<dim3(NPXT, CIN/OCB, BATCH), 256, conv_smem>>>(b1);

    cls_kernel<<<dim3((HW + 255) / 256, BATCH), 256>>>(w2, b2);

    const int topk_smem = 32768*4 + 1024*4 + 1024*8;
    cudaFuncSetAttribute(topk_kernel,
                         cudaFuncAttributeMaxDynamicSharedMemorySize, topk_smem);
    topk_kernel<<<BATCH, 1024, topk_smem>>>();

    const int prop_smem = W3S_FLOATS*4 + PRE*16 + PRE*4 + PRE*4;
    cudaFuncSetAttribute(proposal_kernel,
                         cudaFuncAttributeMaxDynamicSharedMemorySize, prop_smem);
    proposal_kernel<<<BATCH, PRE, prop_smem>>>(w3, b3, out);
}